// round 6
// baseline (speedup 1.0000x reference)
#include <cuda_runtime.h>
#include <cuda_bf16.h>
#include <cstdint>

// Problem constants
#define BB   256
#define TT   100
#define NG   2048
#define NP   512
#define G4   8192          // 4*NG
#define MTR  (BB * TT)     // 25600 rows for dense/dec stages

// ---------------------------------------------------------------------------
// Static device scratch
// ---------------------------------------------------------------------------
__device__ __align__(128) float d_W2pk[2 * G4];
__device__ __align__(128) float d_b2pk[G4];
__device__ __align__(128) __nv_bfloat16 d_Uhi[(size_t)G4 * NG];
__device__ __align__(128) __nv_bfloat16 d_Ulo[(size_t)G4 * NG];
__device__ __align__(128) __nv_bfloat16 d_DWhi[(size_t)NG * NG];
__device__ __align__(128) __nv_bfloat16 d_DWlo[(size_t)NG * NG];
__device__ __align__(128) __nv_bfloat16 d_DChi[(size_t)NP * NG];
__device__ __align__(128) __nv_bfloat16 d_DClo[(size_t)NP * NG];
__device__ __align__(128) __nv_bfloat16 d_hhi[2][(size_t)BB * NG];
__device__ __align__(128) __nv_bfloat16 d_hlo[2][(size_t)BB * NG];
__device__ __align__(128) float d_cbuf[(size_t)BB * NG];
__device__ __align__(128) __nv_bfloat16 d_hshi[(size_t)MTR * NG];
__device__ __align__(128) __nv_bfloat16 d_hslo[(size_t)MTR * NG];
__device__ __align__(128) __nv_bfloat16 d_ghi[(size_t)MTR * NG];
__device__ __align__(128) __nv_bfloat16 d_glo[(size_t)MTR * NG];

__device__ __forceinline__ float sigmoidf_(float z) {
    return 1.0f / (1.0f + __expf(-z));
}

// ---------------------------------------------------------------------------
// PTX helpers (plain sm_103-legal: cp.async / ldmatrix / mma.sync)
// ---------------------------------------------------------------------------
__device__ __forceinline__ uint32_t smem_u32(const void* p) {
    uint32_t a;
    asm("{ .reg .u64 t; cvta.to.shared.u64 t, %1; cvt.u32.u64 %0, t; }" : "=r"(a) : "l"(p));
    return a;
}
#define CP_ASYNC16(dst, src) \
    asm volatile("cp.async.cg.shared.global [%0], [%1], 16;" :: "r"(dst), "l"(src) : "memory")
#define CP_COMMIT()  asm volatile("cp.async.commit_group;" ::: "memory")
#define CP_WAIT(n)   asm volatile("cp.async.wait_group %0;" :: "n"(n) : "memory")

#define LDMX4(r0, r1, r2, r3, addr) \
    asm volatile("ldmatrix.sync.aligned.m8n8.x4.shared.b16 {%0,%1,%2,%3}, [%4];" \
        : "=r"(r0), "=r"(r1), "=r"(r2), "=r"(r3) : "r"(addr))

// NOTE: no volatile — pure register op; "+f" keeps it live, ptxas may schedule.
#define MMA16816(d, a, b0, b1) \
    asm("mma.sync.aligned.m16n8k16.row.col.f32.bf16.bf16.f32 " \
        "{%0,%1,%2,%3}, {%4,%5,%6,%7}, {%8,%9}, {%0,%1,%2,%3};" \
        : "+f"((d)[0]), "+f"((d)[1]), "+f"((d)[2]), "+f"((d)[3]) \
        : "r"((a)[0]), "r"((a)[1]), "r"((a)[2]), "r"((a)[3]), "r"(b0), "r"(b1))

// swizzled byte offset inside a [rows x 128B] tile
__device__ __forceinline__ uint32_t swz(int row, int colbyte) {
    return (uint32_t)((row << 7) + (colbyte ^ ((row & 7) << 4)));
}

// ---------------------------------------------------------------------------
// prep: collapse v->gates (rank-2 trick), gate-interleaved; coalesced reads
// ---------------------------------------------------------------------------
__global__ void prep_w2_k(const float* __restrict__ lstm_W,
                          const float* __restrict__ lstm_b,
                          const float* __restrict__ M_W,
                          const float* __restrict__ M_b) {
    int j = blockIdx.x * blockDim.x + threadIdx.x;
    if (j >= G4) return;
    float w0 = 0.f, w1 = 0.f, bb = 0.f;
#pragma unroll 8
    for (int g = 0; g < NG; g++) {
        float lw = lstm_W[(size_t)g * G4 + j];
        w0 = fmaf(M_W[g],      lw, w0);
        w1 = fmaf(M_W[NG + g], lw, w1);
        bb = fmaf(M_b[g],      lw, bb);
    }
    int n = (j & (NG - 1)) * 4 + (j >> 11);
    d_W2pk[n]      = w0;
    d_W2pk[G4 + n] = w1;
    d_b2pk[n]      = bb + lstm_b[j];
}

// ---------------------------------------------------------------------------
// Fused transpose+split for U (gate-interleaved), dense_W, dec_W. 1 launch.
// ---------------------------------------------------------------------------
__global__ void transp_split_all(const float* __restrict__ U,
                                 const float* __restrict__ DW,
                                 const float* __restrict__ DC) {
    __shared__ float tile[32][33];
    int bid = blockIdx.x;
    const float* src;
    __nv_bfloat16 *hi, *lo;
    int N, bx, by;
    bool gate = false;
    if (bid < 16384) {
        src = U;  hi = d_Uhi;  lo = d_Ulo;  N = G4; gate = true;
        bx = bid & 63; by = bid >> 6;
    } else if (bid < 20480) {
        int l = bid - 16384;
        src = DW; hi = d_DWhi; lo = d_DWlo; N = NG;
        bx = l & 63; by = l >> 6;
    } else {
        int l = bid - 20480;
        src = DC; hi = d_DChi; lo = d_DClo; N = NP;
        bx = l & 63; by = l >> 6;
    }
    const int K = NG;
    int k0 = bx * 32, j0 = by * 32;
    int tx = threadIdx.x, ty = threadIdx.y;
#pragma unroll
    for (int i = 0; i < 4; i++)
        tile[ty + i * 8][tx] = src[(size_t)(k0 + ty + i * 8) * N + j0 + tx];
    __syncthreads();
#pragma unroll
    for (int i = 0; i < 4; i++) {
        int j = j0 + ty + i * 8;
        int n = gate ? ((j & (NG - 1)) * 4 + (j >> 11)) : j;
        float x = tile[tx][ty + i * 8];
        __nv_bfloat16 h = __float2bfloat16(x);
        hi[(size_t)n * K + k0 + tx] = h;
        lo[(size_t)n * K + k0 + tx] = __float2bfloat16(x - __bfloat162float(h));
    }
}

// ---------------------------------------------------------------------------
// Fused encoder: z=0 -> h0 = p0@enc1_W+b (split bf16); z=1 -> c0 fp32
// ---------------------------------------------------------------------------
__global__ __launch_bounds__(256)
void enc_k(const float* __restrict__ p0,
           const float* __restrict__ W1, const float* __restrict__ b1,
           const float* __restrict__ W2, const float* __restrict__ b2,
           __nv_bfloat16* __restrict__ o_hi, __nv_bfloat16* __restrict__ o_lo,
           float* __restrict__ c0) {
    __shared__ float As[16][132];
    __shared__ float Bs[16][64];
    const int z = blockIdx.z;
    const float* A = p0;
    const float* W = z ? W2 : W1;
    const float* bias = z ? b2 : b1;
    const int N = NG, K = NP;
    const int tid = threadIdx.x;
    const int tx = tid & 15;
    const int ty = tid >> 4;
    const int m0 = blockIdx.y * 128;
    const int n0 = blockIdx.x * 64;

    float acc[8][4];
#pragma unroll
    for (int i = 0; i < 8; i++)
#pragma unroll
        for (int j = 0; j < 4; j++) acc[i][j] = 0.f;

    for (int k0 = 0; k0 < K; k0 += 16) {
#pragma unroll
        for (int it = 0; it < 2; it++) {
            int fid = tid + it * 256;
            int m = fid >> 2;
            int kq = (fid & 3) << 2;
            float4 a4 = *(const float4*)(A + (size_t)(m0 + m) * K + k0 + kq);
            As[kq + 0][m] = a4.x; As[kq + 1][m] = a4.y;
            As[kq + 2][m] = a4.z; As[kq + 3][m] = a4.w;
        }
        {
            int kk = tid >> 4;
            int n4 = (tid & 15) << 2;
            *(float4*)&Bs[kk][n4] = *(const float4*)(W + (size_t)(k0 + kk) * N + n0 + n4);
        }
        __syncthreads();
#pragma unroll
        for (int k = 0; k < 16; k++) {
            float a[8], b[4];
            *(float4*)(a)     = *(const float4*)&As[k][ty * 4];
            *(float4*)(a + 4) = *(const float4*)&As[k][64 + ty * 4];
            *(float4*)(b)     = *(const float4*)&Bs[k][tx * 4];
#pragma unroll
            for (int i = 0; i < 8; i++)
#pragma unroll
                for (int j = 0; j < 4; j++)
                    acc[i][j] = fmaf(a[i], b[j], acc[i][j]);
        }
        __syncthreads();
    }

    float4 b4 = *(const float4*)&bias[n0 + tx * 4];
#pragma unroll
    for (int i = 0; i < 8; i++) {
        int m_ = m0 + ((i < 4) ? (ty * 4 + i) : (64 + ty * 4 + i - 4));
#pragma unroll
        for (int j = 0; j < 4; j++) {
            float r = acc[i][j] + ((j == 0) ? b4.x : (j == 1) ? b4.y : (j == 2) ? b4.z : b4.w);
            size_t idx = (size_t)m_ * N + n0 + tx * 4 + j;
            if (z) {
                c0[idx] = r;
            } else {
                __nv_bfloat16 h = __float2bfloat16(r);
                o_hi[idx] = h;
                o_lo[idx] = __float2bfloat16(r - __bfloat162float(h));
            }
        }
    }
}

// ---------------------------------------------------------------------------
// HMMA split-bf16 GEMM, 3-stage cp.async pipeline, 512 threads (16 warps).
// CTA tile 128x128, K chunk 64. Warp grid 4(m) x 4(n), warp tile 32x32.
// Computes Ahi@Bhi^T + Ahi@Blo^T + Alo@Bhi^T (fp32 accum).
// MMA issue ordered BY PRODUCT so no back-to-back RAW on one accumulator.
// MODE 0: fp32 bias out.  MODE 1: relu+bias -> split bf16.  MODE 2: LSTM gate.
// ---------------------------------------------------------------------------
template <int MODE>
__global__ __launch_bounds__(512, 1)
void hmma_gemm(const __nv_bfloat16* __restrict__ Ahi, const __nv_bfloat16* __restrict__ Alo,
               const __nv_bfloat16* __restrict__ Bhi, const __nv_bfloat16* __restrict__ Blo,
               const float* __restrict__ bias, float* __restrict__ Cout,
               int N, int K,
               const float* __restrict__ v, float* __restrict__ c_state,
               __nv_bfloat16* __restrict__ o_hi, __nv_bfloat16* __restrict__ o_lo,
               __nv_bfloat16* __restrict__ hs_hi, __nv_bfloat16* __restrict__ hs_lo,
               int t) {
    extern __shared__ char smem[];
    const uint32_t sb = smem_u32(smem);
    const int tid  = threadIdx.x;
    const int lane = tid & 31;
    const int wid  = tid >> 5;          // 0..15
    const int wm   = wid >> 2;          // 0..3
    const int wn   = wid & 3;           // 0..3
    const int n0 = blockIdx.x * 128;
    const int m0 = blockIdx.y * 128;
    const int NC = K >> 6;              // K/64 chunks

    const int a_r  = (lane & 7) + ((lane >> 3) & 1) * 8;
    const int a_cb = ((lane >> 4) & 1) * 16;
    const int b_r  = (lane & 7) + ((lane >> 4) & 1) * 8;
    const int b_cb = ((lane >> 3) & 1) * 16;

    float acc[2][4][4];
#pragma unroll
    for (int i = 0; i < 2; i++)
#pragma unroll
        for (int j = 0; j < 4; j++)
#pragma unroll
            for (int r = 0; r < 4; r++) acc[i][j][r] = 0.f;

    auto load_stage = [&](int buf, int k0) {
        const __nv_bfloat16* srcs[4] = {Ahi, Alo, Bhi, Blo};
        const int r0s[4] = {m0, m0, n0, n0};
#pragma unroll
        for (int tm = 0; tm < 4; tm++) {
            uint32_t tb = sb + (uint32_t)buf * 65536u + (uint32_t)tm * 16384u;
#pragma unroll
            for (int i = 0; i < 2; i++) {
                int idx = tid + i * 512;
                int row = idx >> 3;
                int c   = idx & 7;
                const void* g = (const void*)(srcs[tm] + (size_t)(r0s[tm] + row) * K + k0 + c * 8);
                CP_ASYNC16(tb + swz(row, c * 16), g);
            }
        }
    };

    // prologue: fill 3 stages
    load_stage(0, 0);   CP_COMMIT();
    load_stage(1, 64);  CP_COMMIT();
    load_stage(2, 128); CP_COMMIT();

    int buf = 0;
    for (int it = 0; it < NC; it++) {
        CP_WAIT(2);
        __syncthreads();
        uint32_t stg = sb + (uint32_t)buf * 65536u;

#pragma unroll 1
        for (int kk = 0; kk < 4; kk++) {
            uint32_t ah[2][4], al[2][4], bh[2][4], bl[2][4];
#pragma unroll
            for (int mi = 0; mi < 2; mi++) {
                uint32_t off = swz(wm * 32 + mi * 16 + a_r, kk * 32 + a_cb);
                LDMX4(ah[mi][0], ah[mi][1], ah[mi][2], ah[mi][3], stg + off);
                LDMX4(al[mi][0], al[mi][1], al[mi][2], al[mi][3], stg + 16384u + off);
            }
#pragma unroll
            for (int bt = 0; bt < 2; bt++) {
                uint32_t off = swz(wn * 32 + bt * 16 + b_r, kk * 32 + b_cb);
                LDMX4(bh[bt][0], bh[bt][1], bh[bt][2], bh[bt][3], stg + 32768u + off);
                LDMX4(bl[bt][0], bl[bt][1], bl[bt][2], bl[bt][3], stg + 49152u + off);
            }
            // product-major issue: consecutive MMAs target different accumulators;
            // a RAW pair on the same acc is 8 MMAs apart.
#pragma unroll
            for (int mi = 0; mi < 2; mi++)
#pragma unroll
                for (int ni = 0; ni < 4; ni++) {
                    int bt = ni >> 1, pr = (ni & 1) * 2;
                    MMA16816(acc[mi][ni], ah[mi], bh[bt][pr], bh[bt][pr + 1]);
                }
#pragma unroll
            for (int mi = 0; mi < 2; mi++)
#pragma unroll
                for (int ni = 0; ni < 4; ni++) {
                    int bt = ni >> 1, pr = (ni & 1) * 2;
                    MMA16816(acc[mi][ni], ah[mi], bl[bt][pr], bl[bt][pr + 1]);
                }
#pragma unroll
            for (int mi = 0; mi < 2; mi++)
#pragma unroll
                for (int ni = 0; ni < 4; ni++) {
                    int bt = ni >> 1, pr = (ni & 1) * 2;
                    MMA16816(acc[mi][ni], al[mi], bh[bt][pr], bh[bt][pr + 1]);
                }
        }
        __syncthreads();
        if (it + 3 < NC) load_stage(buf, (it + 3) * 64);
        CP_COMMIT();
        buf = (buf == 2) ? 0 : buf + 1;
    }

    // ---- Epilogue ----
    const int gi = lane >> 2;
    const int ci = lane & 3;

    if (MODE == 2) {
        const bool isIF = (lane & 1) == 0;
        int rowm[2];
        float vv0[2], vv1[2];
#pragma unroll
        for (int mi = 0; mi < 2; mi++) {
            rowm[mi] = m0 + wm * 32 + mi * 16 + gi + (isIF ? 0 : 8);
            size_t vr = ((size_t)rowm[mi] * TT + t) * 2;
            vv0[mi] = v[vr];
            vv1[mi] = v[vr + 1];
        }
#pragma unroll
        for (int mi = 0; mi < 2; mi++)
#pragma unroll
            for (int ni = 0; ni < 4; ni++) {
                float c0 = acc[mi][ni][0], c1 = acc[mi][ni][1];
                float c2 = acc[mi][ni][2], c3 = acc[mi][ni][3];
                float o0 = __shfl_xor_sync(0xFFFFFFFFu, c0, 1);
                float o1 = __shfl_xor_sync(0xFFFFFFFFu, c1, 1);
                float o2 = __shfl_xor_sync(0xFFFFFFFFu, c2, 1);
                float o3 = __shfl_xor_sync(0xFFFFFFFFu, c3, 1);
                float zi = isIF ? c0 : o2;
                float zf = isIF ? c1 : o3;
                float zg = isIF ? o0 : c2;
                float zo = isIF ? o1 : c3;
                int row  = rowm[mi];
                int qcol = n0 + wn * 32 + ni * 8 + (ci >> 1) * 4;
                float4 q0 = *(const float4*)&d_W2pk[qcol];
                float4 q1 = *(const float4*)&d_W2pk[G4 + qcol];
                float4 qb = *(const float4*)&d_b2pk[qcol];
                zi += fmaf(vv0[mi], q0.x, fmaf(vv1[mi], q1.x, qb.x));
                zf += fmaf(vv0[mi], q0.y, fmaf(vv1[mi], q1.y, qb.y));
                zg += fmaf(vv0[mi], q0.z, fmaf(vv1[mi], q1.z, qb.z));
                zo += fmaf(vv0[mi], q0.w, fmaf(vv1[mi], q1.w, qb.w));
                float ig = sigmoidf_(zi);
                float fg = sigmoidf_(zf);
                float gg = fmaxf(zg, 0.f);
                float og = sigmoidf_(zo);
                int gcol = qcol >> 2;
                size_t cidx = (size_t)row * NG + gcol;
                float cn = fmaf(fg, c_state[cidx], ig * gg);
                c_state[cidx] = cn;
                float h = og * fmaxf(cn, 0.f);
                __nv_bfloat16 hh = __float2bfloat16(h);
                __nv_bfloat16 hl = __float2bfloat16(h - __bfloat162float(hh));
                o_hi[cidx] = hh;
                o_lo[cidx] = hl;
                size_t hsx = ((size_t)row * TT + t) * (size_t)NG + gcol;
                hs_hi[hsx] = hh;
                hs_lo[hsx] = hl;
            }
    } else {
#pragma unroll
        for (int mi = 0; mi < 2; mi++)
#pragma unroll
            for (int ni = 0; ni < 4; ni++) {
                int row0 = m0 + wm * 32 + mi * 16 + gi;
                int col  = n0 + wn * 32 + ni * 8 + ci * 2;
                float bx = bias[col], by = bias[col + 1];
                float r0 = acc[mi][ni][0] + bx, r1 = acc[mi][ni][1] + by;
                float r2 = acc[mi][ni][2] + bx, r3 = acc[mi][ni][3] + by;
                if (MODE == 0) {
                    *(float2*)(Cout + (size_t)row0 * N + col)       = make_float2(r0, r1);
                    *(float2*)(Cout + (size_t)(row0 + 8) * N + col) = make_float2(r2, r3);
                } else {
                    r0 = fmaxf(r0, 0.f); r1 = fmaxf(r1, 0.f);
                    r2 = fmaxf(r2, 0.f); r3 = fmaxf(r3, 0.f);
                    __nv_bfloat16 h0 = __float2bfloat16(r0), h1 = __float2bfloat16(r1);
                    __nv_bfloat16 h2 = __float2bfloat16(r2), h3 = __float2bfloat16(r3);
                    size_t i0 = (size_t)row0 * N + col;
                    size_t i1 = (size_t)(row0 + 8) * N + col;
                    *(__nv_bfloat162*)(o_hi + i0) = __nv_bfloat162(h0, h1);
                    *(__nv_bfloat162*)(o_hi + i1) = __nv_bfloat162(h2, h3);
                    *(__nv_bfloat162*)(o_lo + i0) = __nv_bfloat162(
                        __float2bfloat16(r0 - __bfloat162float(h0)),
                        __float2bfloat16(r1 - __bfloat162float(h1)));
                    *(__nv_bfloat162*)(o_lo + i1) = __nv_bfloat162(
                        __float2bfloat16(r2 - __bfloat162float(h2)),
                        __float2bfloat16(r3 - __bfloat162float(h3)));
                }
            }
    }
}

// ---------------------------------------------------------------------------
extern "C" void kernel_launch(void* const* d_in, const int* in_sizes, int n_in,
                              void* d_out, int out_size) {
    const float* v       = (const float*)d_in[0];
    const float* p0      = (const float*)d_in[1];
    const float* enc1_W  = (const float*)d_in[2];
    const float* enc1_b  = (const float*)d_in[3];
    const float* enc2_W  = (const float*)d_in[4];
    const float* enc2_b  = (const float*)d_in[5];
    const float* M_W     = (const float*)d_in[6];
    const float* M_b     = (const float*)d_in[7];
    const float* lstm_W  = (const float*)d_in[8];
    const float* lstm_U  = (const float*)d_in[9];
    const float* lstm_b  = (const float*)d_in[10];
    const float* dense_W = (const float*)d_in[11];
    const float* dense_b = (const float*)d_in[12];
    const float* dec_W   = (const float*)d_in[13];
    const float* dec_b   = (const float*)d_in[14];
    float* out = (float*)d_out;

    __nv_bfloat16 *Uhi, *Ulo, *DWhi, *DWlo, *DChi, *DClo;
    __nv_bfloat16 *hhi, *hlo, *hshi, *hslo, *ghi, *glo;
    float *cp;
    cudaGetSymbolAddress((void**)&Uhi,  d_Uhi);
    cudaGetSymbolAddress((void**)&Ulo,  d_Ulo);
    cudaGetSymbolAddress((void**)&DWhi, d_DWhi);
    cudaGetSymbolAddress((void**)&DWlo, d_DWlo);
    cudaGetSymbolAddress((void**)&DChi, d_DChi);
    cudaGetSymbolAddress((void**)&DClo, d_DClo);
    cudaGetSymbolAddress((void**)&hhi,  d_hhi);
    cudaGetSymbolAddress((void**)&hlo,  d_hlo);
    cudaGetSymbolAddress((void**)&hshi, d_hshi);
    cudaGetSymbolAddress((void**)&hslo, d_hslo);
    cudaGetSymbolAddress((void**)&ghi,  d_ghi);
    cudaGetSymbolAddress((void**)&glo,  d_glo);
    cudaGetSymbolAddress((void**)&cp,   d_cbuf);

    const int SMEMSZ = 3 * 65536;  // 192 KB, 3-stage pipeline
    cudaFuncSetAttribute(hmma_gemm<0>, cudaFuncAttributeMaxDynamicSharedMemorySize, SMEMSZ);
    cudaFuncSetAttribute(hmma_gemm<1>, cudaFuncAttributeMaxDynamicSharedMemorySize, SMEMSZ);
    cudaFuncSetAttribute(hmma_gemm<2>, cudaFuncAttributeMaxDynamicSharedMemorySize, SMEMSZ);

    // 1) Weight prep
    prep_w2_k<<<G4 / 256, 256>>>(lstm_W, lstm_b, M_W, M_b);
    transp_split_all<<<21504, dim3(32, 8)>>>(lstm_U, dense_W, dec_W);

    // 2) Initial state: h0 split bf16 + c0 fp32
    enc_k<<<dim3(NG / 64, BB / 128, 2), 256>>>(p0, enc1_W, enc1_b, enc2_W, enc2_b,
                                               hhi, hlo, cp);

    // 3) Recurrence: 100 HMMA steps with fused gate epilogue
    const size_t HP = (size_t)BB * NG;
    for (int tstep = 0; tstep < TT; tstep++) {
        int pi = tstep & 1, po = (tstep + 1) & 1;
        hmma_gemm<2><<<dim3(G4 / 128, BB / 128), 512, SMEMSZ>>>(
            hhi + pi * HP, hlo + pi * HP, Uhi, Ulo, nullptr, nullptr, G4, NG,
            v, cp, hhi + po * HP, hlo + po * HP, hshi, hslo, tstep);
    }

    // 4) dense: g = relu(hs @ dense_W + b) -> split bf16
    hmma_gemm<1><<<dim3(NG / 128, MTR / 128), 512, SMEMSZ>>>(
        hshi, hslo, DWhi, DWlo, dense_b, nullptr, NG, NG,
        nullptr, nullptr, ghi, glo, nullptr, nullptr, 0);

    // 5) dec: out = g @ dec_W + b -> fp32
    hmma_gemm<0><<<dim3(NP / 128, MTR / 128), 512, SMEMSZ>>>(
        ghi, glo, DChi, DClo, dec_b, out, NP, NG,
        nullptr, nullptr, nullptr, nullptr, nullptr, nullptr, 0);
}

// round 7
// speedup vs baseline: 1.1114x; 1.1114x over previous
#include <cuda_runtime.h>
#include <cuda_bf16.h>
#include <cstdint>

// Problem constants
#define BB   256
#define TT   100
#define NG   2048
#define NP   512
#define G4   8192          // 4*NG
#define MTR  (BB * TT)     // 25600 rows for dense/dec stages
#define NCH  32            // K/64 chunks (K=2048 for all three big GEMMs)
#define TILEB 32768        // one packed [hi|lo] operand tile: 128 rows x 64 cols x 2B x 2

// ---------------------------------------------------------------------------
// Static device scratch — packed, pre-swizzled operand tiles
// Blob layout: tile_id = (rowblk * NCH + kchunk); within: [hi 16KB | lo 16KB],
// element (r,c) of a 128x64 tile at byte swz(r, c*2).
// ---------------------------------------------------------------------------
__device__ __align__(128) float d_W2pk[2 * G4];
__device__ __align__(128) float d_b2pk[G4];
__device__ __align__(128) char d_Upk [(size_t)(G4 / 128) * NCH * TILEB];   // 64 MB
__device__ __align__(128) char d_DWpk[(size_t)(NG / 128) * NCH * TILEB];   // 16 MB
__device__ __align__(128) char d_DCpk[(size_t)(NP / 128) * NCH * TILEB];   // 4 MB
__device__ __align__(128) char d_hpk [2][(size_t)(BB / 128) * NCH * TILEB];// 2x2 MB ping-pong
__device__ __align__(128) float d_cbuf[(size_t)BB * NG];
__device__ __align__(128) char d_hspk[(size_t)(MTR / 128) * NCH * TILEB];  // 200 MB
__device__ __align__(128) char d_gpk [(size_t)(MTR / 128) * NCH * TILEB];  // 200 MB

__device__ __forceinline__ float sigmoidf_(float z) {
    return 1.0f / (1.0f + __expf(-z));
}

// ---------------------------------------------------------------------------
// PTX helpers (plain sm_90+/sm_103-legal: cp.async.bulk / mbarrier / ldmatrix / mma.sync)
// ---------------------------------------------------------------------------
__device__ __forceinline__ uint32_t smem_u32(const void* p) {
    uint32_t a;
    asm("{ .reg .u64 t; cvta.to.shared.u64 t, %1; cvt.u32.u64 %0, t; }" : "=r"(a) : "l"(p));
    return a;
}
#define MBAR_INIT(addr, cnt) \
    asm volatile("mbarrier.init.shared.b64 [%0], %1;" :: "r"(addr), "r"((uint32_t)(cnt)) : "memory")
#define MBAR_EXPECT(addr, bytes) \
    asm volatile("mbarrier.arrive.expect_tx.shared.b64 _, [%0], %1;" :: "r"(addr), "r"((uint32_t)(bytes)) : "memory")
#define BULK_CP(dst, src, bytes, mbar) \
    asm volatile("cp.async.bulk.shared::cta.global.mbarrier::complete_tx::bytes [%0], [%1], %2, [%3];" \
        :: "r"(dst), "l"(src), "r"((uint32_t)(bytes)), "r"(mbar) : "memory")
#define MBAR_WAIT(addr, parity) do { \
    uint32_t _m = (addr); uint32_t _p = (parity); uint32_t _done; \
    asm volatile("{\n\t.reg .pred p;\n\t" \
        "mbarrier.try_wait.parity.acquire.cta.shared::cta.b64 p, [%1], %2;\n\t" \
        "selp.b32 %0, 1, 0, p;\n\t}" : "=r"(_done) : "r"(_m), "r"(_p) : "memory"); \
    if (!_done) { \
        asm volatile("{\n\t.reg .pred P1;\n\t" \
            "WL_%=:\n\t" \
            "mbarrier.try_wait.parity.acquire.cta.shared::cta.b64 P1, [%0], %1, 0x989680;\n\t" \
            "@P1 bra.uni WD_%=;\n\t" \
            "bra.uni WL_%=;\n\t" \
            "WD_%=:\n\t}" :: "r"(_m), "r"(_p) : "memory"); \
    } } while (0)

#define LDMX4(r0, r1, r2, r3, addr) \
    asm volatile("ldmatrix.sync.aligned.m8n8.x4.shared.b16 {%0,%1,%2,%3}, [%4];" \
        : "=r"(r0), "=r"(r1), "=r"(r2), "=r"(r3) : "r"(addr))

#define MMA16816(d, a, b0, b1) \
    asm("mma.sync.aligned.m16n8k16.row.col.f32.bf16.bf16.f32 " \
        "{%0,%1,%2,%3}, {%4,%5,%6,%7}, {%8,%9}, {%0,%1,%2,%3};" \
        : "+f"((d)[0]), "+f"((d)[1]), "+f"((d)[2]), "+f"((d)[3]) \
        : "r"((a)[0]), "r"((a)[1]), "r"((a)[2]), "r"((a)[3]), "r"(b0), "r"(b1))

// swizzled byte offset inside a [128 rows x 128B] tile
__device__ __forceinline__ uint32_t swz(int row, int colbyte) {
    return (uint32_t)((row << 7) + (colbyte ^ ((row & 7) << 4)));
}
// packed blob byte offset for element (row, col) of a [rows x 2048] bf16 matrix
__device__ __forceinline__ size_t pk_off(int row, int col) {
    return (size_t)((row >> 7) * NCH + (col >> 6)) * TILEB + swz(row & 127, (col & 63) * 2);
}

// ---------------------------------------------------------------------------
// prep: collapse v->gates (rank-2 trick), gate-interleaved; coalesced reads
// ---------------------------------------------------------------------------
__global__ void prep_w2_k(const float* __restrict__ lstm_W,
                          const float* __restrict__ lstm_b,
                          const float* __restrict__ M_W,
                          const float* __restrict__ M_b) {
    int j = blockIdx.x * blockDim.x + threadIdx.x;
    if (j >= G4) return;
    float w0 = 0.f, w1 = 0.f, bb = 0.f;
#pragma unroll 8
    for (int g = 0; g < NG; g++) {
        float lw = lstm_W[(size_t)g * G4 + j];
        w0 = fmaf(M_W[g],      lw, w0);
        w1 = fmaf(M_W[NG + g], lw, w1);
        bb = fmaf(M_b[g],      lw, bb);
    }
    int n = (j & (NG - 1)) * 4 + (j >> 11);
    d_W2pk[n]      = w0;
    d_W2pk[G4 + n] = w1;
    d_b2pk[n]      = bb + lstm_b[j];
}

// ---------------------------------------------------------------------------
// Fused transpose+split+pack for U (gate-interleaved), dense_W, dec_W.
// Writes packed pre-swizzled [hi|lo] tiles.
// ---------------------------------------------------------------------------
__global__ void transp_split_all(const float* __restrict__ U,
                                 const float* __restrict__ DW,
                                 const float* __restrict__ DC) {
    __shared__ float tile[32][33];
    int bid = blockIdx.x;
    const float* src;
    char* pk;
    int N, bx, by;
    bool gate = false;
    if (bid < 16384) {
        src = U;  pk = d_Upk;  N = G4; gate = true;
        bx = bid & 63; by = bid >> 6;
    } else if (bid < 20480) {
        int l = bid - 16384;
        src = DW; pk = d_DWpk; N = NG;
        bx = l & 63; by = l >> 6;
    } else {
        int l = bid - 20480;
        src = DC; pk = d_DCpk; N = NP;
        bx = l & 63; by = l >> 6;
    }
    int k0 = bx * 32, j0 = by * 32;
    int tx = threadIdx.x, ty = threadIdx.y;   // (32, 8)
#pragma unroll
    for (int i = 0; i < 4; i++)
        tile[ty + i * 8][tx] = src[(size_t)(k0 + ty + i * 8) * N + j0 + tx];
    __syncthreads();
#pragma unroll
    for (int i = 0; i < 4; i++) {
        int j = j0 + ty + i * 8;
        int n = gate ? ((j & (NG - 1)) * 4 + (j >> 11)) : j;
        int k = k0 + tx;
        float x = tile[tx][ty + i * 8];       // src[k][j]
        __nv_bfloat16 h = __float2bfloat16(x);
        size_t off = pk_off(n, k);
        *(__nv_bfloat16*)(pk + off)         = h;
        *(__nv_bfloat16*)(pk + off + 16384) = __float2bfloat16(x - __bfloat162float(h));
    }
}

// ---------------------------------------------------------------------------
// Fused encoder: z=0 -> h0 = p0@enc1_W+b (packed split bf16); z=1 -> c0 fp32
// ---------------------------------------------------------------------------
__global__ __launch_bounds__(256)
void enc_k(const float* __restrict__ p0,
           const float* __restrict__ W1, const float* __restrict__ b1,
           const float* __restrict__ W2, const float* __restrict__ b2,
           char* __restrict__ hpk0, float* __restrict__ c0) {
    __shared__ float As[16][132];
    __shared__ float Bs[16][64];
    const int z = blockIdx.z;
    const float* A = p0;
    const float* W = z ? W2 : W1;
    const float* bias = z ? b2 : b1;
    const int N = NG, K = NP;
    const int tid = threadIdx.x;
    const int tx = tid & 15;
    const int ty = tid >> 4;
    const int m0 = blockIdx.y * 128;
    const int n0 = blockIdx.x * 64;

    float acc[8][4];
#pragma unroll
    for (int i = 0; i < 8; i++)
#pragma unroll
        for (int j = 0; j < 4; j++) acc[i][j] = 0.f;

    for (int k0 = 0; k0 < K; k0 += 16) {
#pragma unroll
        for (int it = 0; it < 2; it++) {
            int fid = tid + it * 256;
            int m = fid >> 2;
            int kq = (fid & 3) << 2;
            float4 a4 = *(const float4*)(A + (size_t)(m0 + m) * K + k0 + kq);
            As[kq + 0][m] = a4.x; As[kq + 1][m] = a4.y;
            As[kq + 2][m] = a4.z; As[kq + 3][m] = a4.w;
        }
        {
            int kk = tid >> 4;
            int n4 = (tid & 15) << 2;
            *(float4*)&Bs[kk][n4] = *(const float4*)(W + (size_t)(k0 + kk) * N + n0 + n4);
        }
        __syncthreads();
#pragma unroll
        for (int k = 0; k < 16; k++) {
            float a[8], b[4];
            *(float4*)(a)     = *(const float4*)&As[k][ty * 4];
            *(float4*)(a + 4) = *(const float4*)&As[k][64 + ty * 4];
            *(float4*)(b)     = *(const float4*)&Bs[k][tx * 4];
#pragma unroll
            for (int i = 0; i < 8; i++)
#pragma unroll
                for (int j = 0; j < 4; j++)
                    acc[i][j] = fmaf(a[i], b[j], acc[i][j]);
        }
        __syncthreads();
    }

    float4 b4 = *(const float4*)&bias[n0 + tx * 4];
#pragma unroll
    for (int i = 0; i < 8; i++) {
        int m_ = m0 + ((i < 4) ? (ty * 4 + i) : (64 + ty * 4 + i - 4));
#pragma unroll
        for (int j = 0; j < 4; j++) {
            float r = acc[i][j] + ((j == 0) ? b4.x : (j == 1) ? b4.y : (j == 2) ? b4.z : b4.w);
            int col = n0 + tx * 4 + j;
            if (z) {
                c0[(size_t)m_ * NG + col] = r;
            } else {
                __nv_bfloat16 h = __float2bfloat16(r);
                size_t off = pk_off(m_, col);
                *(__nv_bfloat16*)(hpk0 + off)         = h;
                *(__nv_bfloat16*)(hpk0 + off + 16384) = __float2bfloat16(r - __bfloat162float(h));
            }
        }
    }
}

// ---------------------------------------------------------------------------
// HMMA split-bf16 GEMM, 3-stage BULK-COPY pipeline, 512 threads (16 warps).
// CTA tile 128x128, K chunk 64. Warp grid 4(m) x 4(n), warp tile 32x32.
// Operands arrive as packed pre-swizzled 32KB [hi|lo] tiles via cp.async.bulk:
// 2 bulk ops per stage instead of 4096 cp.async (kills the LSU-issue bottleneck).
// MODE 0: fp32 bias out (dec). MODE 1: relu+bias -> packed g (dense).
// MODE 2: fused LSTM gate epilogue -> packed h + packed hs.
// ---------------------------------------------------------------------------
template <int MODE>
__global__ __launch_bounds__(512, 1)
void hmma_gemm(const char* __restrict__ Apk, const char* __restrict__ Bpk,
               const float* __restrict__ bias, float* __restrict__ Cout,
               int Nout,
               const float* __restrict__ v, float* __restrict__ c_state,
               char* __restrict__ hpk_out, char* __restrict__ hspk_out,
               char* __restrict__ gpk_out,
               int t) {
    extern __shared__ char smem[];
    __shared__ __align__(8) uint64_t mbars[3];
    const uint32_t sb = smem_u32(smem);
    const int tid  = threadIdx.x;
    const int lane = tid & 31;
    const int wid  = tid >> 5;          // 0..15
    const int wm   = wid >> 2;          // 0..3
    const int wn   = wid & 3;           // 0..3
    const int n0 = blockIdx.x * 128;
    const int m0 = blockIdx.y * 128;
    const int NC = NCH;                 // 32 chunks (K=2048)

    const int a_r  = (lane & 7) + ((lane >> 3) & 1) * 8;
    const int a_cb = ((lane >> 4) & 1) * 16;
    const int b_r  = (lane & 7) + ((lane >> 4) & 1) * 8;
    const int b_cb = ((lane >> 3) & 1) * 16;

    float acc[2][4][4];
#pragma unroll
    for (int i = 0; i < 2; i++)
#pragma unroll
        for (int j = 0; j < 4; j++)
#pragma unroll
            for (int r = 0; r < 4; r++) acc[i][j][r] = 0.f;

    const char* Abase = Apk + (size_t)(m0 >> 7) * NCH * TILEB;
    const char* Bbase = Bpk + (size_t)(n0 >> 7) * NCH * TILEB;

    auto issue = [&](int bufi, int c) {
        uint32_t mb = smem_u32(&mbars[bufi]);
        MBAR_EXPECT(mb, 2 * TILEB);
        uint32_t dst = sb + (uint32_t)bufi * 65536u;
        BULK_CP(dst,          Abase + (size_t)c * TILEB, TILEB, mb);
        BULK_CP(dst + 32768u, Bbase + (size_t)c * TILEB, TILEB, mb);
    };

    if (tid == 0) {
        MBAR_INIT(smem_u32(&mbars[0]), 1);
        MBAR_INIT(smem_u32(&mbars[1]), 1);
        MBAR_INIT(smem_u32(&mbars[2]), 1);
    }
    __syncthreads();
    if (tid == 0) { issue(0, 0); issue(1, 1); issue(2, 2); }

    int buf = 0;
    for (int it = 0; it < NC; it++) {
        MBAR_WAIT(smem_u32(&mbars[buf]), (it / 3) & 1);
        uint32_t stg = sb + (uint32_t)buf * 65536u;

#pragma unroll 1
        for (int kk = 0; kk < 4; kk++) {
            uint32_t ah[2][4], al[2][4], bh[2][4], bl[2][4];
#pragma unroll
            for (int mi = 0; mi < 2; mi++) {
                uint32_t off = swz(wm * 32 + mi * 16 + a_r, kk * 32 + a_cb);
                LDMX4(ah[mi][0], ah[mi][1], ah[mi][2], ah[mi][3], stg + off);
                LDMX4(al[mi][0], al[mi][1], al[mi][2], al[mi][3], stg + 16384u + off);
            }
#pragma unroll
            for (int bt = 0; bt < 2; bt++) {
                uint32_t off = swz(wn * 32 + bt * 16 + b_r, kk * 32 + b_cb);
                LDMX4(bh[bt][0], bh[bt][1], bh[bt][2], bh[bt][3], stg + 32768u + off);
                LDMX4(bl[bt][0], bl[bt][1], bl[bt][2], bl[bt][3], stg + 49152u + off);
            }
#pragma unroll
            for (int mi = 0; mi < 2; mi++)
#pragma unroll
                for (int ni = 0; ni < 4; ni++) {
                    int bt = ni >> 1, pr = (ni & 1) * 2;
                    MMA16816(acc[mi][ni], ah[mi], bh[bt][pr], bh[bt][pr + 1]);
                }
#pragma unroll
            for (int mi = 0; mi < 2; mi++)
#pragma unroll
                for (int ni = 0; ni < 4; ni++) {
                    int bt = ni >> 1, pr = (ni & 1) * 2;
                    MMA16816(acc[mi][ni], ah[mi], bl[bt][pr], bl[bt][pr + 1]);
                }
#pragma unroll
            for (int mi = 0; mi < 2; mi++)
#pragma unroll
                for (int ni = 0; ni < 4; ni++) {
                    int bt = ni >> 1, pr = (ni & 1) * 2;
                    MMA16816(acc[mi][ni], al[mi], bh[bt][pr], bh[bt][pr + 1]);
                }
        }
        __syncthreads();            // all warps done reading buf
        if (tid == 0 && it + 3 < NC) issue(buf, it + 3);
        buf = (buf == 2) ? 0 : buf + 1;
    }

    // ---- Epilogue ----
    const int gi = lane >> 2;
    const int ci = lane & 3;

    if (MODE == 2) {
        const bool isIF = (lane & 1) == 0;
        int rowm[2];
        float vv0[2], vv1[2];
#pragma unroll
        for (int mi = 0; mi < 2; mi++) {
            rowm[mi] = m0 + wm * 32 + mi * 16 + gi + (isIF ? 0 : 8);
            size_t vr = ((size_t)rowm[mi] * TT + t) * 2;
            vv0[mi] = v[vr];
            vv1[mi] = v[vr + 1];
        }
#pragma unroll
        for (int mi = 0; mi < 2; mi++)
#pragma unroll
            for (int ni = 0; ni < 4; ni++) {
                float c0 = acc[mi][ni][0], c1 = acc[mi][ni][1];
                float c2 = acc[mi][ni][2], c3 = acc[mi][ni][3];
                float o0 = __shfl_xor_sync(0xFFFFFFFFu, c0, 1);
                float o1 = __shfl_xor_sync(0xFFFFFFFFu, c1, 1);
                float o2 = __shfl_xor_sync(0xFFFFFFFFu, c2, 1);
                float o3 = __shfl_xor_sync(0xFFFFFFFFu, c3, 1);
                float zi = isIF ? c0 : o2;
                float zf = isIF ? c1 : o3;
                float zg = isIF ? o0 : c2;
                float zo = isIF ? o1 : c3;
                int row  = rowm[mi];
                int qcol = n0 + wn * 32 + ni * 8 + (ci >> 1) * 4;
                float4 q0 = *(const float4*)&d_W2pk[qcol];
                float4 q1 = *(const float4*)&d_W2pk[G4 + qcol];
                float4 qb = *(const float4*)&d_b2pk[qcol];
                zi += fmaf(vv0[mi], q0.x, fmaf(vv1[mi], q1.x, qb.x));
                zf += fmaf(vv0[mi], q0.y, fmaf(vv1[mi], q1.y, qb.y));
                zg += fmaf(vv0[mi], q0.z, fmaf(vv1[mi], q1.z, qb.z));
                zo += fmaf(vv0[mi], q0.w, fmaf(vv1[mi], q1.w, qb.w));
                float ig = sigmoidf_(zi);
                float fg = sigmoidf_(zf);
                float gg = fmaxf(zg, 0.f);
                float og = sigmoidf_(zo);
                int gcol = qcol >> 2;
                size_t cidx = (size_t)row * NG + gcol;
                float cn = fmaf(fg, c_state[cidx], ig * gg);
                c_state[cidx] = cn;
                float h = og * fmaxf(cn, 0.f);
                __nv_bfloat16 hh = __float2bfloat16(h);
                __nv_bfloat16 hl = __float2bfloat16(h - __bfloat162float(hh));
                size_t ho = pk_off(row, gcol);
                *(__nv_bfloat16*)(hpk_out + ho)         = hh;
                *(__nv_bfloat16*)(hpk_out + ho + 16384) = hl;
                int hsrow = row * TT + t;
                size_t so = pk_off(hsrow, gcol);
                *(__nv_bfloat16*)(hspk_out + so)         = hh;
                *(__nv_bfloat16*)(hspk_out + so + 16384) = hl;
            }
    } else {
#pragma unroll
        for (int mi = 0; mi < 2; mi++)
#pragma unroll
            for (int ni = 0; ni < 4; ni++) {
                int row0 = m0 + wm * 32 + mi * 16 + gi;
                int col  = n0 + wn * 32 + ni * 8 + ci * 2;
                float bx = bias[col], by = bias[col + 1];
                float r0 = acc[mi][ni][0] + bx, r1 = acc[mi][ni][1] + by;
                float r2 = acc[mi][ni][2] + bx, r3 = acc[mi][ni][3] + by;
                if (MODE == 0) {
                    *(float2*)(Cout + (size_t)row0 * Nout + col)       = make_float2(r0, r1);
                    *(float2*)(Cout + (size_t)(row0 + 8) * Nout + col) = make_float2(r2, r3);
                } else {
                    r0 = fmaxf(r0, 0.f); r1 = fmaxf(r1, 0.f);
                    r2 = fmaxf(r2, 0.f); r3 = fmaxf(r3, 0.f);
                    __nv_bfloat16 h0 = __float2bfloat16(r0), h1 = __float2bfloat16(r1);
                    __nv_bfloat16 h2 = __float2bfloat16(r2), h3 = __float2bfloat16(r3);
                    size_t o0 = pk_off(row0, col);
                    size_t o1 = pk_off(row0 + 8, col);
                    *(__nv_bfloat162*)(gpk_out + o0) = __nv_bfloat162(h0, h1);
                    *(__nv_bfloat162*)(gpk_out + o1) = __nv_bfloat162(h2, h3);
                    *(__nv_bfloat162*)(gpk_out + o0 + 16384) = __nv_bfloat162(
                        __float2bfloat16(r0 - __bfloat162float(h0)),
                        __float2bfloat16(r1 - __bfloat162float(h1)));
                    *(__nv_bfloat162*)(gpk_out + o1 + 16384) = __nv_bfloat162(
                        __float2bfloat16(r2 - __bfloat162float(h2)),
                        __float2bfloat16(r3 - __bfloat162float(h3)));
                }
            }
    }
}

// ---------------------------------------------------------------------------
extern "C" void kernel_launch(void* const* d_in, const int* in_sizes, int n_in,
                              void* d_out, int out_size) {
    const float* v       = (const float*)d_in[0];
    const float* p0      = (const float*)d_in[1];
    const float* enc1_W  = (const float*)d_in[2];
    const float* enc1_b  = (const float*)d_in[3];
    const float* enc2_W  = (const float*)d_in[4];
    const float* enc2_b  = (const float*)d_in[5];
    const float* M_W     = (const float*)d_in[6];
    const float* M_b     = (const float*)d_in[7];
    const float* lstm_W  = (const float*)d_in[8];
    const float* lstm_U  = (const float*)d_in[9];
    const float* lstm_b  = (const float*)d_in[10];
    const float* dense_W = (const float*)d_in[11];
    const float* dense_b = (const float*)d_in[12];
    const float* dec_W   = (const float*)d_in[13];
    const float* dec_b   = (const float*)d_in[14];
    float* out = (float*)d_out;

    char *Upk, *DWpk, *DCpk, *hpk, *hspk, *gpk;
    float *cp;
    cudaGetSymbolAddress((void**)&Upk,  d_Upk);
    cudaGetSymbolAddress((void**)&DWpk, d_DWpk);
    cudaGetSymbolAddress((void**)&DCpk, d_DCpk);
    cudaGetSymbolAddress((void**)&hpk,  d_hpk);
    cudaGetSymbolAddress((void**)&hspk, d_hspk);
    cudaGetSymbolAddress((void**)&gpk,  d_gpk);
    cudaGetSymbolAddress((void**)&cp,   d_cbuf);

    const int SMEMSZ = 3 * 65536;  // 192 KB, 3-stage bulk pipeline
    cudaFuncSetAttribute(hmma_gemm<0>, cudaFuncAttributeMaxDynamicSharedMemorySize, SMEMSZ);
    cudaFuncSetAttribute(hmma_gemm<1>, cudaFuncAttributeMaxDynamicSharedMemorySize, SMEMSZ);
    cudaFuncSetAttribute(hmma_gemm<2>, cudaFuncAttributeMaxDynamicSharedMemorySize, SMEMSZ);

    // 1) Weight prep: rank-2 collapse + transpose/split/pack (pre-swizzled tiles)
    prep_w2_k<<<G4 / 256, 256>>>(lstm_W, lstm_b, M_W, M_b);
    transp_split_all<<<21504, dim3(32, 8)>>>(lstm_U, dense_W, dec_W);

    // 2) Initial state: h0 packed split bf16 + c0 fp32
    enc_k<<<dim3(NG / 64, BB / 128, 2), 256>>>(p0, enc1_W, enc1_b, enc2_W, enc2_b,
                                               hpk, cp);

    // 3) Recurrence: 100 HMMA steps, bulk-fed, fused gate epilogue
    const size_t HP = (size_t)(BB / 128) * NCH * TILEB;
    for (int tstep = 0; tstep < TT; tstep++) {
        int pi = tstep & 1, po = (tstep + 1) & 1;
        hmma_gemm<2><<<dim3(G4 / 128, BB / 128), 512, SMEMSZ>>>(
            hpk + pi * HP, Upk, nullptr, nullptr, 0,
            v, cp, hpk + po * HP, hspk, nullptr, tstep);
    }

    // 4) dense: g = relu(hs @ dense_W + b) -> packed split bf16
    hmma_gemm<1><<<dim3(NG / 128, MTR / 128), 512, SMEMSZ>>>(
        hspk, DWpk, dense_b, nullptr, 0,
        nullptr, nullptr, nullptr, nullptr, gpk, 0);

    // 5) dec: out = g @ dec_W + b -> fp32
    hmma_gemm<0><<<dim3(NP / 128, MTR / 128), 512, SMEMSZ>>>(
        gpk, DCpk, dec_b, out, NP,
        nullptr, nullptr, nullptr, nullptr, nullptr, 0);
}

// round 8
// speedup vs baseline: 1.1588x; 1.0426x over previous
#include <cuda_runtime.h>
#include <cuda_bf16.h>
#include <cstdint>

// Problem constants
#define BB   256
#define TT   100
#define NG   2048
#define NP   512
#define G4   8192          // 4*NG
#define MTR  (BB * TT)     // 25600 rows for dense/dec stages
#define NCH  32            // K/64 chunks (K=2048 for all three big GEMMs)
#define TILEB 32768        // one packed [hi|lo] operand tile: 128 rows x 64 cols x 2B x 2

// ---------------------------------------------------------------------------
// Static device scratch — packed, pre-swizzled operand tiles
// ---------------------------------------------------------------------------
__device__ __align__(128) float d_W2pk[2 * G4];
__device__ __align__(128) float d_b2pk[G4];
__device__ __align__(128) char d_Upk [(size_t)(G4 / 128) * NCH * TILEB];   // 64 MB
__device__ __align__(128) char d_DWpk[(size_t)(NG / 128) * NCH * TILEB];   // 16 MB
__device__ __align__(128) char d_DCpk[(size_t)(NP / 128) * NCH * TILEB];   // 4 MB
__device__ __align__(128) char d_hpk [2][(size_t)(BB / 128) * NCH * TILEB];
__device__ __align__(128) float d_cbuf[(size_t)BB * NG];
__device__ __align__(128) char d_hspk[(size_t)(MTR / 128) * NCH * TILEB];  // 200 MB
__device__ __align__(128) char d_gpk [(size_t)(MTR / 128) * NCH * TILEB];  // 200 MB

__device__ __forceinline__ float sigmoidf_(float z) {
    return 1.0f / (1.0f + __expf(-z));
}

// ---------------------------------------------------------------------------
// PTX helpers
// ---------------------------------------------------------------------------
__device__ __forceinline__ uint32_t smem_u32(const void* p) {
    uint32_t a;
    asm("{ .reg .u64 t; cvta.to.shared.u64 t, %1; cvt.u32.u64 %0, t; }" : "=r"(a) : "l"(p));
    return a;
}
#define MBAR_INIT(addr, cnt) \
    asm volatile("mbarrier.init.shared.b64 [%0], %1;" :: "r"(addr), "r"((uint32_t)(cnt)) : "memory")
#define MBAR_EXPECT(addr, bytes) \
    asm volatile("mbarrier.arrive.expect_tx.shared.b64 _, [%0], %1;" :: "r"(addr), "r"((uint32_t)(bytes)) : "memory")
#define BULK_CP(dst, src, bytes, mbar) \
    asm volatile("cp.async.bulk.shared::cta.global.mbarrier::complete_tx::bytes [%0], [%1], %2, [%3];" \
        :: "r"(dst), "l"(src), "r"((uint32_t)(bytes)), "r"(mbar) : "memory")
#define MBAR_WAIT(addr, parity) do { \
    uint32_t _m = (addr); uint32_t _p = (parity); uint32_t _done; \
    asm volatile("{\n\t.reg .pred p;\n\t" \
        "mbarrier.try_wait.parity.acquire.cta.shared::cta.b64 p, [%1], %2;\n\t" \
        "selp.b32 %0, 1, 0, p;\n\t}" : "=r"(_done) : "r"(_m), "r"(_p) : "memory"); \
    if (!_done) { \
        asm volatile("{\n\t.reg .pred P1;\n\t" \
            "WL_%=:\n\t" \
            "mbarrier.try_wait.parity.acquire.cta.shared::cta.b64 P1, [%0], %1, 0x989680;\n\t" \
            "@P1 bra.uni WD_%=;\n\t" \
            "bra.uni WL_%=;\n\t" \
            "WD_%=:\n\t}" :: "r"(_m), "r"(_p) : "memory"); \
    } } while (0)

#define LDMX4(r0, r1, r2, r3, addr) \
    asm volatile("ldmatrix.sync.aligned.m8n8.x4.shared.b16 {%0,%1,%2,%3}, [%4];" \
        : "=r"(r0), "=r"(r1), "=r"(r2), "=r"(r3) : "r"(addr))

#define MMA16816(d, a, b0, b1) \
    asm("mma.sync.aligned.m16n8k16.row.col.f32.bf16.bf16.f32 " \
        "{%0,%1,%2,%3}, {%4,%5,%6,%7}, {%8,%9}, {%0,%1,%2,%3};" \
        : "+f"((d)[0]), "+f"((d)[1]), "+f"((d)[2]), "+f"((d)[3]) \
        : "r"((a)[0]), "r"((a)[1]), "r"((a)[2]), "r"((a)[3]), "r"(b0), "r"(b1))

// swizzled byte offset inside a [128 rows x 128B] tile
__device__ __forceinline__ uint32_t swz(int row, int colbyte) {
    return (uint32_t)((row << 7) + (colbyte ^ ((row & 7) << 4)));
}
// packed blob byte offset for element (row, col) of a [rows x 2048] bf16 matrix
__device__ __forceinline__ size_t pk_off(int row, int col) {
    return (size_t)((row >> 7) * NCH + (col >> 6)) * TILEB + swz(row & 127, (col & 63) * 2);
}

// ---------------------------------------------------------------------------
// prep: collapse v->gates (rank-2 trick), gate-interleaved; coalesced reads
// ---------------------------------------------------------------------------
__global__ void prep_w2_k(const float* __restrict__ lstm_W,
                          const float* __restrict__ lstm_b,
                          const float* __restrict__ M_W,
                          const float* __restrict__ M_b) {
    int j = blockIdx.x * blockDim.x + threadIdx.x;
    if (j >= G4) return;
    float w0 = 0.f, w1 = 0.f, bb = 0.f;
#pragma unroll 8
    for (int g = 0; g < NG; g++) {
        float lw = lstm_W[(size_t)g * G4 + j];
        w0 = fmaf(M_W[g],      lw, w0);
        w1 = fmaf(M_W[NG + g], lw, w1);
        bb = fmaf(M_b[g],      lw, bb);
    }
    int n = (j & (NG - 1)) * 4 + (j >> 11);
    d_W2pk[n]      = w0;
    d_W2pk[G4 + n] = w1;
    d_b2pk[n]      = bb + lstm_b[j];
}

// ---------------------------------------------------------------------------
// Fused transpose+split+pack for U (gate-interleaved), dense_W, dec_W.
// ---------------------------------------------------------------------------
__global__ void transp_split_all(const float* __restrict__ U,
                                 const float* __restrict__ DW,
                                 const float* __restrict__ DC) {
    __shared__ float tile[32][33];
    int bid = blockIdx.x;
    const float* src;
    char* pk;
    int N, bx, by;
    bool gate = false;
    if (bid < 16384) {
        src = U;  pk = d_Upk;  N = G4; gate = true;
        bx = bid & 63; by = bid >> 6;
    } else if (bid < 20480) {
        int l = bid - 16384;
        src = DW; pk = d_DWpk; N = NG;
        bx = l & 63; by = l >> 6;
    } else {
        int l = bid - 20480;
        src = DC; pk = d_DCpk; N = NP;
        bx = l & 63; by = l >> 6;
    }
    int k0 = bx * 32, j0 = by * 32;
    int tx = threadIdx.x, ty = threadIdx.y;   // (32, 8)
#pragma unroll
    for (int i = 0; i < 4; i++)
        tile[ty + i * 8][tx] = src[(size_t)(k0 + ty + i * 8) * N + j0 + tx];
    __syncthreads();
#pragma unroll
    for (int i = 0; i < 4; i++) {
        int j = j0 + ty + i * 8;
        int n = gate ? ((j & (NG - 1)) * 4 + (j >> 11)) : j;
        int k = k0 + tx;
        float x = tile[tx][ty + i * 8];       // src[k][j]
        __nv_bfloat16 h = __float2bfloat16(x);
        size_t off = pk_off(n, k);
        *(__nv_bfloat16*)(pk + off)         = h;
        *(__nv_bfloat16*)(pk + off + 16384) = __float2bfloat16(x - __bfloat162float(h));
    }
}

// ---------------------------------------------------------------------------
// Fused encoder: z=0 -> h0 = p0@enc1_W+b (packed split bf16); z=1 -> c0 fp32
// ---------------------------------------------------------------------------
__global__ __launch_bounds__(256)
void enc_k(const float* __restrict__ p0,
           const float* __restrict__ W1, const float* __restrict__ b1,
           const float* __restrict__ W2, const float* __restrict__ b2,
           char* __restrict__ hpk0, float* __restrict__ c0) {
    __shared__ float As[16][132];
    __shared__ float Bs[16][64];
    const int z = blockIdx.z;
    const float* A = p0;
    const float* W = z ? W2 : W1;
    const float* bias = z ? b2 : b1;
    const int N = NG, K = NP;
    const int tid = threadIdx.x;
    const int tx = tid & 15;
    const int ty = tid >> 4;
    const int m0 = blockIdx.y * 128;
    const int n0 = blockIdx.x * 64;

    float acc[8][4];
#pragma unroll
    for (int i = 0; i < 8; i++)
#pragma unroll
        for (int j = 0; j < 4; j++) acc[i][j] = 0.f;

    for (int k0 = 0; k0 < K; k0 += 16) {
#pragma unroll
        for (int it = 0; it < 2; it++) {
            int fid = tid + it * 256;
            int m = fid >> 2;
            int kq = (fid & 3) << 2;
            float4 a4 = *(const float4*)(A + (size_t)(m0 + m) * K + k0 + kq);
            As[kq + 0][m] = a4.x; As[kq + 1][m] = a4.y;
            As[kq + 2][m] = a4.z; As[kq + 3][m] = a4.w;
        }
        {
            int kk = tid >> 4;
            int n4 = (tid & 15) << 2;
            *(float4*)&Bs[kk][n4] = *(const float4*)(W + (size_t)(k0 + kk) * N + n0 + n4);
        }
        __syncthreads();
#pragma unroll
        for (int k = 0; k < 16; k++) {
            float a[8], b[4];
            *(float4*)(a)     = *(const float4*)&As[k][ty * 4];
            *(float4*)(a + 4) = *(const float4*)&As[k][64 + ty * 4];
            *(float4*)(b)     = *(const float4*)&Bs[k][tx * 4];
#pragma unroll
            for (int i = 0; i < 8; i++)
#pragma unroll
                for (int j = 0; j < 4; j++)
                    acc[i][j] = fmaf(a[i], b[j], acc[i][j]);
        }
        __syncthreads();
    }

    float4 b4 = *(const float4*)&bias[n0 + tx * 4];
#pragma unroll
    for (int i = 0; i < 8; i++) {
        int m_ = m0 + ((i < 4) ? (ty * 4 + i) : (64 + ty * 4 + i - 4));
#pragma unroll
        for (int j = 0; j < 4; j++) {
            float r = acc[i][j] + ((j == 0) ? b4.x : (j == 1) ? b4.y : (j == 2) ? b4.z : b4.w);
            int col = n0 + tx * 4 + j;
            if (z) {
                c0[(size_t)m_ * NG + col] = r;
            } else {
                __nv_bfloat16 h = __float2bfloat16(r);
                size_t off = pk_off(m_, col);
                *(__nv_bfloat16*)(hpk0 + off)         = h;
                *(__nv_bfloat16*)(hpk0 + off + 16384) = __float2bfloat16(r - __bfloat162float(h));
            }
        }
    }
}

// ---------------------------------------------------------------------------
// Fragment load/compute macros (compile-time slot index -> no local spills)
// ---------------------------------------------------------------------------
#define LOAD_FRAGS(S, KK) \
    { \
        _Pragma("unroll") \
        for (int mi = 0; mi < 4; mi++) { \
            uint32_t off = swz(wm * 64 + mi * 16 + a_r, (KK) * 32 + a_cb); \
            LDMX4(ah[S][mi][0], ah[S][mi][1], ah[S][mi][2], ah[S][mi][3], stg + off); \
            LDMX4(al[S][mi][0], al[S][mi][1], al[S][mi][2], al[S][mi][3], stg + 16384u + off); \
        } \
        _Pragma("unroll") \
        for (int bt = 0; bt < 2; bt++) { \
            uint32_t off = swz(wn * 32 + bt * 16 + b_r, (KK) * 32 + b_cb); \
            LDMX4(bh[S][bt][0], bh[S][bt][1], bh[S][bt][2], bh[S][bt][3], stg + 32768u + off); \
            LDMX4(bl[S][bt][0], bl[S][bt][1], bl[S][bt][2], bl[S][bt][3], stg + 49152u + off); \
        } \
    }

#define MMA_ALL(S) \
    { \
        _Pragma("unroll") \
        for (int mi = 0; mi < 4; mi++) \
        _Pragma("unroll") \
        for (int ni = 0; ni < 4; ni++) { \
            int bt = ni >> 1, pr = (ni & 1) * 2; \
            MMA16816(acc[mi][ni], ah[S][mi], bh[S][bt][pr], bh[S][bt][pr + 1]); \
        } \
        _Pragma("unroll") \
        for (int mi = 0; mi < 4; mi++) \
        _Pragma("unroll") \
        for (int ni = 0; ni < 4; ni++) { \
            int bt = ni >> 1, pr = (ni & 1) * 2; \
            MMA16816(acc[mi][ni], ah[S][mi], bl[S][bt][pr], bl[S][bt][pr + 1]); \
        } \
        _Pragma("unroll") \
        for (int mi = 0; mi < 4; mi++) \
        _Pragma("unroll") \
        for (int ni = 0; ni < 4; ni++) { \
            int bt = ni >> 1, pr = (ni & 1) * 2; \
            MMA16816(acc[mi][ni], al[S][mi], bh[S][bt][pr], bh[S][bt][pr + 1]); \
        } \
    }

// ---------------------------------------------------------------------------
// HMMA split-bf16 GEMM, 3-stage bulk-copy pipeline, 256 threads (8 warps).
// CTA tile 128x128, K chunk 64. Warp grid 2(m) x 4(n), warp tile 64x32.
// Register fragments DOUBLE-BUFFERED across kk: LDSM for kk+1 issued before
// MMAs of kk so the tensor pipe stays fed through ldmatrix latency.
// MODE 0: fp32 bias out (dec). MODE 1: relu+bias -> packed g (dense).
// MODE 2: fused LSTM gate epilogue -> packed h + packed hs.
// ---------------------------------------------------------------------------
template <int MODE>
__global__ __launch_bounds__(256, 1)
void hmma_gemm(const char* __restrict__ Apk, const char* __restrict__ Bpk,
               const float* __restrict__ bias, float* __restrict__ Cout,
               int Nout,
               const float* __restrict__ v, float* __restrict__ c_state,
               char* __restrict__ hpk_out, char* __restrict__ hspk_out,
               char* __restrict__ gpk_out,
               int t) {
    extern __shared__ char smem[];
    __shared__ __align__(8) uint64_t mbars[3];
    const uint32_t sb = smem_u32(smem);
    const int tid  = threadIdx.x;
    const int lane = tid & 31;
    const int wid  = tid >> 5;          // 0..7
    const int wm   = wid >> 2;          // 0..1
    const int wn   = wid & 3;           // 0..3
    const int n0 = blockIdx.x * 128;
    const int m0 = blockIdx.y * 128;
    const int NC = NCH;

    const int a_r  = (lane & 7) + ((lane >> 3) & 1) * 8;
    const int a_cb = ((lane >> 4) & 1) * 16;
    const int b_r  = (lane & 7) + ((lane >> 4) & 1) * 8;
    const int b_cb = ((lane >> 3) & 1) * 16;

    float acc[4][4][4];
#pragma unroll
    for (int i = 0; i < 4; i++)
#pragma unroll
        for (int j = 0; j < 4; j++)
#pragma unroll
            for (int r = 0; r < 4; r++) acc[i][j][r] = 0.f;

    const char* Abase = Apk + (size_t)(m0 >> 7) * NCH * TILEB;
    const char* Bbase = Bpk + (size_t)(n0 >> 7) * NCH * TILEB;

    auto issue = [&](int bufi, int c) {
        uint32_t mb = smem_u32(&mbars[bufi]);
        MBAR_EXPECT(mb, 2 * TILEB);
        uint32_t dst = sb + (uint32_t)bufi * 65536u;
        BULK_CP(dst,          Abase + (size_t)c * TILEB, TILEB, mb);
        BULK_CP(dst + 32768u, Bbase + (size_t)c * TILEB, TILEB, mb);
    };

    if (tid == 0) {
        MBAR_INIT(smem_u32(&mbars[0]), 1);
        MBAR_INIT(smem_u32(&mbars[1]), 1);
        MBAR_INIT(smem_u32(&mbars[2]), 1);
    }
    __syncthreads();
    if (tid == 0) { issue(0, 0); issue(1, 1); issue(2, 2); }

    int buf = 0;
    for (int it = 0; it < NC; it++) {
        MBAR_WAIT(smem_u32(&mbars[buf]), (it / 3) & 1);
        uint32_t stg = sb + (uint32_t)buf * 65536u;

        uint32_t ah[2][4][4], al[2][4][4], bh[2][2][4], bl[2][2][4];
        // kk pipeline: prefetch kk+1's fragments before kk's MMAs
        LOAD_FRAGS(0, 0);
        LOAD_FRAGS(1, 1); MMA_ALL(0);
        LOAD_FRAGS(0, 2); MMA_ALL(1);
        LOAD_FRAGS(1, 3); MMA_ALL(0 ^ 0); // slot 0 holds kk=2
        // note: slot for kk=2 is 0, kk=3 is 1
        MMA_ALL(1);

        __syncthreads();            // all warps done reading buf
        if (tid == 0 && it + 3 < NC) issue(buf, it + 3);
        buf = (buf == 2) ? 0 : buf + 1;
    }

    // ---- Epilogue ----
    const int gi = lane >> 2;
    const int ci = lane & 3;

    if (MODE == 2) {
        const bool isIF = (lane & 1) == 0;
        int rowm[4];
        float vv0[4], vv1[4];
#pragma unroll
        for (int mi = 0; mi < 4; mi++) {
            rowm[mi] = m0 + wm * 64 + mi * 16 + gi + (isIF ? 0 : 8);
            size_t vr = ((size_t)rowm[mi] * TT + t) * 2;
            vv0[mi] = v[vr];
            vv1[mi] = v[vr + 1];
        }
#pragma unroll
        for (int mi = 0; mi < 4; mi++)
#pragma unroll
            for (int ni = 0; ni < 4; ni++) {
                float c0 = acc[mi][ni][0], c1 = acc[mi][ni][1];
                float c2 = acc[mi][ni][2], c3 = acc[mi][ni][3];
                float o0 = __shfl_xor_sync(0xFFFFFFFFu, c0, 1);
                float o1 = __shfl_xor_sync(0xFFFFFFFFu, c1, 1);
                float o2 = __shfl_xor_sync(0xFFFFFFFFu, c2, 1);
                float o3 = __shfl_xor_sync(0xFFFFFFFFu, c3, 1);
                float zi = isIF ? c0 : o2;
                float zf = isIF ? c1 : o3;
                float zg = isIF ? o0 : c2;
                float zo = isIF ? o1 : c3;
                int row  = rowm[mi];
                int qcol = n0 + wn * 32 + ni * 8 + (ci >> 1) * 4;
                float4 q0 = *(const float4*)&d_W2pk[qcol];
                float4 q1 = *(const float4*)&d_W2pk[G4 + qcol];
                float4 qb = *(const float4*)&d_b2pk[qcol];
                zi += fmaf(vv0[mi], q0.x, fmaf(vv1[mi], q1.x, qb.x));
                zf += fmaf(vv0[mi], q0.y, fmaf(vv1[mi], q1.y, qb.y));
                zg += fmaf(vv0[mi], q0.z, fmaf(vv1[mi], q1.z, qb.z));
                zo += fmaf(vv0[mi], q0.w, fmaf(vv1[mi], q1.w, qb.w));
                float ig = sigmoidf_(zi);
                float fg = sigmoidf_(zf);
                float gg = fmaxf(zg, 0.f);
                float og = sigmoidf_(zo);
                int gcol = qcol >> 2;
                size_t cidx = (size_t)row * NG + gcol;
                float cn = fmaf(fg, c_state[cidx], ig * gg);
                c_state[cidx] = cn;
                float h = og * fmaxf(cn, 0.f);
                __nv_bfloat16 hh = __float2bfloat16(h);
                __nv_bfloat16 hl = __float2bfloat16(h - __bfloat162float(hh));
                size_t ho = pk_off(row, gcol);
                *(__nv_bfloat16*)(hpk_out + ho)         = hh;
                *(__nv_bfloat16*)(hpk_out + ho + 16384) = hl;
                int hsrow = row * TT + t;
                size_t so = pk_off(hsrow, gcol);
                *(__nv_bfloat16*)(hspk_out + so)         = hh;
                *(__nv_bfloat16*)(hspk_out + so + 16384) = hl;
            }
    } else {
#pragma unroll
        for (int mi = 0; mi < 4; mi++)
#pragma unroll
            for (int ni = 0; ni < 4; ni++) {
                int row0 = m0 + wm * 64 + mi * 16 + gi;
                int col  = n0 + wn * 32 + ni * 8 + ci * 2;
                float bx = bias[col], by = bias[col + 1];
                float r0 = acc[mi][ni][0] + bx, r1 = acc[mi][ni][1] + by;
                float r2 = acc[mi][ni][2] + bx, r3 = acc[mi][ni][3] + by;
                if (MODE == 0) {
                    *(float2*)(Cout + (size_t)row0 * Nout + col)       = make_float2(r0, r1);
                    *(float2*)(Cout + (size_t)(row0 + 8) * Nout + col) = make_float2(r2, r3);
                } else {
                    r0 = fmaxf(r0, 0.f); r1 = fmaxf(r1, 0.f);
                    r2 = fmaxf(r2, 0.f); r3 = fmaxf(r3, 0.f);
                    __nv_bfloat16 h0 = __float2bfloat16(r0), h1 = __float2bfloat16(r1);
                    __nv_bfloat16 h2 = __float2bfloat16(r2), h3 = __float2bfloat16(r3);
                    size_t o0 = pk_off(row0, col);
                    size_t o1 = pk_off(row0 + 8, col);
                    *(__nv_bfloat162*)(gpk_out + o0) = __nv_bfloat162(h0, h1);
                    *(__nv_bfloat162*)(gpk_out + o1) = __nv_bfloat162(h2, h3);
                    *(__nv_bfloat162*)(gpk_out + o0 + 16384) = __nv_bfloat162(
                        __float2bfloat16(r0 - __bfloat162float(h0)),
                        __float2bfloat16(r1 - __bfloat162float(h1)));
                    *(__nv_bfloat162*)(gpk_out + o1 + 16384) = __nv_bfloat162(
                        __float2bfloat16(r2 - __bfloat162float(h2)),
                        __float2bfloat16(r3 - __bfloat162float(h3)));
                }
            }
    }
}

// ---------------------------------------------------------------------------
extern "C" void kernel_launch(void* const* d_in, const int* in_sizes, int n_in,
                              void* d_out, int out_size) {
    const float* v       = (const float*)d_in[0];
    const float* p0      = (const float*)d_in[1];
    const float* enc1_W  = (const float*)d_in[2];
    const float* enc1_b  = (const float*)d_in[3];
    const float* enc2_W  = (const float*)d_in[4];
    const float* enc2_b  = (const float*)d_in[5];
    const float* M_W     = (const float*)d_in[6];
    const float* M_b     = (const float*)d_in[7];
    const float* lstm_W  = (const float*)d_in[8];
    const float* lstm_U  = (const float*)d_in[9];
    const float* lstm_b  = (const float*)d_in[10];
    const float* dense_W = (const float*)d_in[11];
    const float* dense_b = (const float*)d_in[12];
    const float* dec_W   = (const float*)d_in[13];
    const float* dec_b   = (const float*)d_in[14];
    float* out = (float*)d_out;

    char *Upk, *DWpk, *DCpk, *hpk, *hspk, *gpk;
    float *cp;
    cudaGetSymbolAddress((void**)&Upk,  d_Upk);
    cudaGetSymbolAddress((void**)&DWpk, d_DWpk);
    cudaGetSymbolAddress((void**)&DCpk, d_DCpk);
    cudaGetSymbolAddress((void**)&hpk,  d_hpk);
    cudaGetSymbolAddress((void**)&hspk, d_hspk);
    cudaGetSymbolAddress((void**)&gpk,  d_gpk);
    cudaGetSymbolAddress((void**)&cp,   d_cbuf);

    const int SMEMSZ = 3 * 65536;  // 192 KB, 3-stage bulk pipeline
    cudaFuncSetAttribute(hmma_gemm<0>, cudaFuncAttributeMaxDynamicSharedMemorySize, SMEMSZ);
    cudaFuncSetAttribute(hmma_gemm<1>, cudaFuncAttributeMaxDynamicSharedMemorySize, SMEMSZ);
    cudaFuncSetAttribute(hmma_gemm<2>, cudaFuncAttributeMaxDynamicSharedMemorySize, SMEMSZ);

    // 1) Weight prep
    prep_w2_k<<<G4 / 256, 256>>>(lstm_W, lstm_b, M_W, M_b);
    transp_split_all<<<21504, dim3(32, 8)>>>(lstm_U, dense_W, dec_W);

    // 2) Initial state: h0 packed split bf16 + c0 fp32
    enc_k<<<dim3(NG / 64, BB / 128, 2), 256>>>(p0, enc1_W, enc1_b, enc2_W, enc2_b,
                                               hpk, cp);

    // 3) Recurrence: 100 HMMA steps, bulk-fed, fragment-pipelined
    const size_t HP = (size_t)(BB / 128) * NCH * TILEB;
    for (int tstep = 0; tstep < TT; tstep++) {
        int pi = tstep & 1, po = (tstep + 1) & 1;
        hmma_gemm<2><<<dim3(G4 / 128, BB / 128), 256, SMEMSZ>>>(
            hpk + pi * HP, Upk, nullptr, nullptr, 0,
            v, cp, hpk + po * HP, hspk, nullptr, tstep);
    }

    // 4) dense: g = relu(hs @ dense_W + b) -> packed split bf16
    hmma_gemm<1><<<dim3(NG / 128, MTR / 128), 256, SMEMSZ>>>(
        hspk, DWpk, dense_b, nullptr, 0,
        nullptr, nullptr, nullptr, nullptr, gpk, 0);

    // 5) dec: out = g @ dec_W + b -> fp32
    hmma_gemm<0><<<dim3(NP / 128, MTR / 128), 256, SMEMSZ>>>(
        gpk, DCpk, dec_b, out, NP,
        nullptr, nullptr, nullptr, nullptr, nullptr, 0);
}

// round 9
// speedup vs baseline: 1.2058x; 1.0406x over previous
#include <cuda_runtime.h>
#include <cuda_bf16.h>
#include <cstdint>

// Problem constants
#define BB   256
#define TT   100
#define NG   2048
#define NP   512
#define G4   8192          // 4*NG
#define MTR  (BB * TT)     // 25600 rows for dense/dec stages
#define NCH  32            // K/64 chunks (K=2048 for all three big GEMMs)
#define TILEB 32768        // one packed [hi|lo] operand tile: 128 rows x 64 cols x 2B x 2

// ---------------------------------------------------------------------------
// Static device scratch — packed, pre-swizzled operand tiles
// ---------------------------------------------------------------------------
__device__ __align__(128) float d_W2pk[2 * G4];
__device__ __align__(128) float d_b2pk[G4];
__device__ __align__(128) char d_Upk [(size_t)(G4 / 128) * NCH * TILEB];   // 64 MB
__device__ __align__(128) char d_DWpk[(size_t)(NG / 128) * NCH * TILEB];   // 16 MB
__device__ __align__(128) char d_DCpk[(size_t)(NP / 128) * NCH * TILEB];   // 4 MB
__device__ __align__(128) char d_hpk [2][(size_t)(BB / 128) * NCH * TILEB];
__device__ __align__(128) float d_cbuf[(size_t)BB * NG];
__device__ __align__(128) char d_hspk[(size_t)(MTR / 128) * NCH * TILEB];  // 200 MB
__device__ __align__(128) char d_gpk [(size_t)(MTR / 128) * NCH * TILEB];  // 200 MB

__device__ __forceinline__ float sigmoidf_(float z) {
    return 1.0f / (1.0f + __expf(-z));
}

// ---------------------------------------------------------------------------
// PTX helpers
// ---------------------------------------------------------------------------
__device__ __forceinline__ uint32_t smem_u32(const void* p) {
    uint32_t a;
    asm("{ .reg .u64 t; cvta.to.shared.u64 t, %1; cvt.u32.u64 %0, t; }" : "=r"(a) : "l"(p));
    return a;
}
#define MBAR_INIT(addr, cnt) \
    asm volatile("mbarrier.init.shared.b64 [%0], %1;" :: "r"(addr), "r"((uint32_t)(cnt)) : "memory")
#define MBAR_EXPECT(addr, bytes) \
    asm volatile("mbarrier.arrive.expect_tx.shared.b64 _, [%0], %1;" :: "r"(addr), "r"((uint32_t)(bytes)) : "memory")
#define MBAR_ARRIVE(addr) \
    asm volatile("mbarrier.arrive.shared.b64 _, [%0];" :: "r"(addr) : "memory")
#define BULK_CP(dst, src, bytes, mbar) \
    asm volatile("cp.async.bulk.shared::cta.global.mbarrier::complete_tx::bytes [%0], [%1], %2, [%3];" \
        :: "r"(dst), "l"(src), "r"((uint32_t)(bytes)), "r"(mbar) : "memory")
#define MBAR_WAIT(addr, parity) do { \
    uint32_t _m = (addr); uint32_t _p = (parity); uint32_t _done; \
    asm volatile("{\n\t.reg .pred p;\n\t" \
        "mbarrier.try_wait.parity.acquire.cta.shared::cta.b64 p, [%1], %2;\n\t" \
        "selp.b32 %0, 1, 0, p;\n\t}" : "=r"(_done) : "r"(_m), "r"(_p) : "memory"); \
    if (!_done) { \
        asm volatile("{\n\t.reg .pred P1;\n\t" \
            "WL_%=:\n\t" \
            "mbarrier.try_wait.parity.acquire.cta.shared::cta.b64 P1, [%0], %1, 0x989680;\n\t" \
            "@P1 bra.uni WD_%=;\n\t" \
            "bra.uni WL_%=;\n\t" \
            "WD_%=:\n\t}" :: "r"(_m), "r"(_p) : "memory"); \
    } } while (0)

#define LDMX4(r0, r1, r2, r3, addr) \
    asm volatile("ldmatrix.sync.aligned.m8n8.x4.shared.b16 {%0,%1,%2,%3}, [%4];" \
        : "=r"(r0), "=r"(r1), "=r"(r2), "=r"(r3) : "r"(addr))

#define MMA16816(d, a, b0, b1) \
    asm("mma.sync.aligned.m16n8k16.row.col.f32.bf16.bf16.f32 " \
        "{%0,%1,%2,%3}, {%4,%5,%6,%7}, {%8,%9}, {%0,%1,%2,%3};" \
        : "+f"((d)[0]), "+f"((d)[1]), "+f"((d)[2]), "+f"((d)[3]) \
        : "r"((a)[0]), "r"((a)[1]), "r"((a)[2]), "r"((a)[3]), "r"(b0), "r"(b1))

// swizzled byte offset inside a [128 rows x 128B] tile
__device__ __forceinline__ uint32_t swz(int row, int colbyte) {
    return (uint32_t)((row << 7) + (colbyte ^ ((row & 7) << 4)));
}
// packed blob byte offset for element (row, col) of a [rows x 2048] bf16 matrix
__device__ __forceinline__ size_t pk_off(int row, int col) {
    return (size_t)((row >> 7) * NCH + (col >> 6)) * TILEB + swz(row & 127, (col & 63) * 2);
}

// ---------------------------------------------------------------------------
// prep: collapse v->gates (rank-2 trick), gate-interleaved; coalesced reads
// ---------------------------------------------------------------------------
__global__ void prep_w2_k(const float* __restrict__ lstm_W,
                          const float* __restrict__ lstm_b,
                          const float* __restrict__ M_W,
                          const float* __restrict__ M_b) {
    int j = blockIdx.x * blockDim.x + threadIdx.x;
    if (j >= G4) return;
    float w0 = 0.f, w1 = 0.f, bb = 0.f;
#pragma unroll 8
    for (int g = 0; g < NG; g++) {
        float lw = lstm_W[(size_t)g * G4 + j];
        w0 = fmaf(M_W[g],      lw, w0);
        w1 = fmaf(M_W[NG + g], lw, w1);
        bb = fmaf(M_b[g],      lw, bb);
    }
    int n = (j & (NG - 1)) * 4 + (j >> 11);
    d_W2pk[n]      = w0;
    d_W2pk[G4 + n] = w1;
    d_b2pk[n]      = bb + lstm_b[j];
}

// ---------------------------------------------------------------------------
// Fused transpose+split+pack for U (gate-interleaved), dense_W, dec_W.
// ---------------------------------------------------------------------------
__global__ void transp_split_all(const float* __restrict__ U,
                                 const float* __restrict__ DW,
                                 const float* __restrict__ DC) {
    __shared__ float tile[32][33];
    int bid = blockIdx.x;
    const float* src;
    char* pk;
    int N, bx, by;
    bool gate = false;
    if (bid < 16384) {
        src = U;  pk = d_Upk;  N = G4; gate = true;
        bx = bid & 63; by = bid >> 6;
    } else if (bid < 20480) {
        int l = bid - 16384;
        src = DW; pk = d_DWpk; N = NG;
        bx = l & 63; by = l >> 6;
    } else {
        int l = bid - 20480;
        src = DC; pk = d_DCpk; N = NP;
        bx = l & 63; by = l >> 6;
    }
    int k0 = bx * 32, j0 = by * 32;
    int tx = threadIdx.x, ty = threadIdx.y;   // (32, 8)
#pragma unroll
    for (int i = 0; i < 4; i++)
        tile[ty + i * 8][tx] = src[(size_t)(k0 + ty + i * 8) * N + j0 + tx];
    __syncthreads();
#pragma unroll
    for (int i = 0; i < 4; i++) {
        int j = j0 + ty + i * 8;
        int n = gate ? ((j & (NG - 1)) * 4 + (j >> 11)) : j;
        int k = k0 + tx;
        float x = tile[tx][ty + i * 8];       // src[k][j]
        __nv_bfloat16 h = __float2bfloat16(x);
        size_t off = pk_off(n, k);
        *(__nv_bfloat16*)(pk + off)         = h;
        *(__nv_bfloat16*)(pk + off + 16384) = __float2bfloat16(x - __bfloat162float(h));
    }
}

// ---------------------------------------------------------------------------
// Fused encoder: z=0 -> h0 = p0@enc1_W+b (packed split bf16); z=1 -> c0 fp32
// ---------------------------------------------------------------------------
__global__ __launch_bounds__(256)
void enc_k(const float* __restrict__ p0,
           const float* __restrict__ W1, const float* __restrict__ b1,
           const float* __restrict__ W2, const float* __restrict__ b2,
           char* __restrict__ hpk0, float* __restrict__ c0) {
    __shared__ float As[16][132];
    __shared__ float Bs[16][64];
    const int z = blockIdx.z;
    const float* A = p0;
    const float* W = z ? W2 : W1;
    const float* bias = z ? b2 : b1;
    const int N = NG, K = NP;
    const int tid = threadIdx.x;
    const int tx = tid & 15;
    const int ty = tid >> 4;
    const int m0 = blockIdx.y * 128;
    const int n0 = blockIdx.x * 64;

    float acc[8][4];
#pragma unroll
    for (int i = 0; i < 8; i++)
#pragma unroll
        for (int j = 0; j < 4; j++) acc[i][j] = 0.f;

    for (int k0 = 0; k0 < K; k0 += 16) {
#pragma unroll
        for (int it = 0; it < 2; it++) {
            int fid = tid + it * 256;
            int m = fid >> 2;
            int kq = (fid & 3) << 2;
            float4 a4 = *(const float4*)(A + (size_t)(m0 + m) * K + k0 + kq);
            As[kq + 0][m] = a4.x; As[kq + 1][m] = a4.y;
            As[kq + 2][m] = a4.z; As[kq + 3][m] = a4.w;
        }
        {
            int kk = tid >> 4;
            int n4 = (tid & 15) << 2;
            *(float4*)&Bs[kk][n4] = *(const float4*)(W + (size_t)(k0 + kk) * N + n0 + n4);
        }
        __syncthreads();
#pragma unroll
        for (int k = 0; k < 16; k++) {
            float a[8], b[4];
            *(float4*)(a)     = *(const float4*)&As[k][ty * 4];
            *(float4*)(a + 4) = *(const float4*)&As[k][64 + ty * 4];
            *(float4*)(b)     = *(const float4*)&Bs[k][tx * 4];
#pragma unroll
            for (int i = 0; i < 8; i++)
#pragma unroll
                for (int j = 0; j < 4; j++)
                    acc[i][j] = fmaf(a[i], b[j], acc[i][j]);
        }
        __syncthreads();
    }

    float4 b4 = *(const float4*)&bias[n0 + tx * 4];
#pragma unroll
    for (int i = 0; i < 8; i++) {
        int m_ = m0 + ((i < 4) ? (ty * 4 + i) : (64 + ty * 4 + i - 4));
#pragma unroll
        for (int j = 0; j < 4; j++) {
            float r = acc[i][j] + ((j == 0) ? b4.x : (j == 1) ? b4.y : (j == 2) ? b4.z : b4.w);
            int col = n0 + tx * 4 + j;
            if (z) {
                c0[(size_t)m_ * NG + col] = r;
            } else {
                __nv_bfloat16 h = __float2bfloat16(r);
                size_t off = pk_off(m_, col);
                *(__nv_bfloat16*)(hpk0 + off)         = h;
                *(__nv_bfloat16*)(hpk0 + off + 16384) = __float2bfloat16(r - __bfloat162float(h));
            }
        }
    }
}

// ---------------------------------------------------------------------------
// Fragment load/compute macros
// ---------------------------------------------------------------------------
#define LOAD_FRAGS(S, KK) \
    { \
        _Pragma("unroll") \
        for (int mi = 0; mi < 4; mi++) { \
            uint32_t off = swz(wm * 64 + mi * 16 + a_r, (KK) * 32 + a_cb); \
            LDMX4(ah[S][mi][0], ah[S][mi][1], ah[S][mi][2], ah[S][mi][3], stg + off); \
            LDMX4(al[S][mi][0], al[S][mi][1], al[S][mi][2], al[S][mi][3], stg + 16384u + off); \
        } \
        _Pragma("unroll") \
        for (int bt = 0; bt < 2; bt++) { \
            uint32_t off = swz(wn * 32 + bt * 16 + b_r, (KK) * 32 + b_cb); \
            LDMX4(bh[S][bt][0], bh[S][bt][1], bh[S][bt][2], bh[S][bt][3], stg + 32768u + off); \
            LDMX4(bl[S][bt][0], bl[S][bt][1], bl[S][bt][2], bl[S][bt][3], stg + 49152u + off); \
        } \
    }

#define MMA_ALL(S) \
    { \
        _Pragma("unroll") \
        for (int mi = 0; mi < 4; mi++) \
        _Pragma("unroll") \
        for (int ni = 0; ni < 4; ni++) { \
            int bt = ni >> 1, pr = (ni & 1) * 2; \
            MMA16816(acc[mi][ni], ah[S][mi], bh[S][bt][pr], bh[S][bt][pr + 1]); \
        } \
        _Pragma("unroll") \
        for (int mi = 0; mi < 4; mi++) \
        _Pragma("unroll") \
        for (int ni = 0; ni < 4; ni++) { \
            int bt = ni >> 1, pr = (ni & 1) * 2; \
            MMA16816(acc[mi][ni], ah[S][mi], bl[S][bt][pr], bl[S][bt][pr + 1]); \
        } \
        _Pragma("unroll") \
        for (int mi = 0; mi < 4; mi++) \
        _Pragma("unroll") \
        for (int ni = 0; ni < 4; ni++) { \
            int bt = ni >> 1, pr = (ni & 1) * 2; \
            MMA16816(acc[mi][ni], al[S][mi], bh[S][bt][pr], bh[S][bt][pr + 1]); \
        } \
    }

// ---------------------------------------------------------------------------
// HMMA split-bf16 GEMM: warp-specialized producer/consumer, NO CTA barriers
// in the mainloop. 288 threads = 8 compute warps (2m x 4n, 64x32 tiles) + 1
// producer warp driving cp.async.bulk through full/empty mbarrier pairs.
// 3-stage 192KB smem ring; fragment double-buffering across kk.
// MODE 0: fp32 bias out (dec). MODE 1: relu+bias -> packed g (dense).
// MODE 2: fused LSTM gate epilogue -> packed h + packed hs.
// ---------------------------------------------------------------------------
template <int MODE>
__global__ __launch_bounds__(288, 1)
void hmma_gemm(const char* __restrict__ Apk, const char* __restrict__ Bpk,
               const float* __restrict__ bias, float* __restrict__ Cout,
               int Nout,
               const float* __restrict__ v, float* __restrict__ c_state,
               char* __restrict__ hpk_out, char* __restrict__ hspk_out,
               char* __restrict__ gpk_out,
               int t) {
    extern __shared__ char smem[];
    __shared__ __align__(8) uint64_t mbars[6];   // full[0..2], empty[0..2]
    const uint32_t sb = smem_u32(smem);
    const int tid  = threadIdx.x;
    const int lane = tid & 31;
    const int wid  = tid >> 5;          // 0..8
    const int n0 = blockIdx.x * 128;
    const int m0 = blockIdx.y * 128;
    const int NC = NCH;

    const char* Abase = Apk + (size_t)(m0 >> 7) * NCH * TILEB;
    const char* Bbase = Bpk + (size_t)(n0 >> 7) * NCH * TILEB;

    if (tid == 0) {
#pragma unroll
        for (int i = 0; i < 3; i++) {
            MBAR_INIT(smem_u32(&mbars[i]), 1);       // full: 1 tx-completion
            MBAR_INIT(smem_u32(&mbars[3 + i]), 8);   // empty: 8 warp arrivals
        }
    }
    __syncthreads();

    if (wid == 8) {
        // ---- producer warp ----
        if (lane == 0) {
            for (int c = 0; c < NC; c++) {
                int i = c % 3;
                if (c >= 3) MBAR_WAIT(smem_u32(&mbars[3 + i]), ((c / 3) - 1) & 1);
                uint32_t mb = smem_u32(&mbars[i]);
                MBAR_EXPECT(mb, 2 * TILEB);
                uint32_t dst = sb + (uint32_t)i * 65536u;
                BULK_CP(dst,          Abase + (size_t)c * TILEB, TILEB, mb);
                BULK_CP(dst + 32768u, Bbase + (size_t)c * TILEB, TILEB, mb);
            }
        }
        return;
    }

    // ---- compute warps ----
    const int wm = wid >> 2;            // 0..1
    const int wn = wid & 3;             // 0..3
    const int a_r  = (lane & 7) + ((lane >> 3) & 1) * 8;
    const int a_cb = ((lane >> 4) & 1) * 16;
    const int b_r  = (lane & 7) + ((lane >> 4) & 1) * 8;
    const int b_cb = ((lane >> 3) & 1) * 16;

    float acc[4][4][4];
#pragma unroll
    for (int i = 0; i < 4; i++)
#pragma unroll
        for (int j = 0; j < 4; j++)
#pragma unroll
            for (int r = 0; r < 4; r++) acc[i][j][r] = 0.f;

    int buf = 0;
    for (int it = 0; it < NC; it++) {
        MBAR_WAIT(smem_u32(&mbars[buf]), (it / 3) & 1);
        uint32_t stg = sb + (uint32_t)buf * 65536u;

        uint32_t ah[2][4][4], al[2][4][4], bh[2][2][4], bl[2][2][4];
        LOAD_FRAGS(0, 0);
        LOAD_FRAGS(1, 1); MMA_ALL(0);
        LOAD_FRAGS(0, 2); MMA_ALL(1);
        LOAD_FRAGS(1, 3); MMA_ALL(0);
        MMA_ALL(1);

        __syncwarp();
        if (lane == 0) MBAR_ARRIVE(smem_u32(&mbars[3 + buf]));
        buf = (buf == 2) ? 0 : buf + 1;
    }

    // ---- Epilogue ----
    const int gi = lane >> 2;
    const int ci = lane & 3;

    if (MODE == 2) {
        const bool isIF = (lane & 1) == 0;
        int rowm[4];
        float vv0[4], vv1[4];
#pragma unroll
        for (int mi = 0; mi < 4; mi++) {
            rowm[mi] = m0 + wm * 64 + mi * 16 + gi + (isIF ? 0 : 8);
            size_t vr = ((size_t)rowm[mi] * TT + t) * 2;
            vv0[mi] = v[vr];
            vv1[mi] = v[vr + 1];
        }
#pragma unroll
        for (int mi = 0; mi < 4; mi++)
#pragma unroll
            for (int ni = 0; ni < 4; ni++) {
                float c0 = acc[mi][ni][0], c1 = acc[mi][ni][1];
                float c2 = acc[mi][ni][2], c3 = acc[mi][ni][3];
                float o0 = __shfl_xor_sync(0xFFFFFFFFu, c0, 1);
                float o1 = __shfl_xor_sync(0xFFFFFFFFu, c1, 1);
                float o2 = __shfl_xor_sync(0xFFFFFFFFu, c2, 1);
                float o3 = __shfl_xor_sync(0xFFFFFFFFu, c3, 1);
                float zi = isIF ? c0 : o2;
                float zf = isIF ? c1 : o3;
                float zg = isIF ? o0 : c2;
                float zo = isIF ? o1 : c3;
                int row  = rowm[mi];
                int qcol = n0 + wn * 32 + ni * 8 + (ci >> 1) * 4;
                float4 q0 = *(const float4*)&d_W2pk[qcol];
                float4 q1 = *(const float4*)&d_W2pk[G4 + qcol];
                float4 qb = *(const float4*)&d_b2pk[qcol];
                zi += fmaf(vv0[mi], q0.x, fmaf(vv1[mi], q1.x, qb.x));
                zf += fmaf(vv0[mi], q0.y, fmaf(vv1[mi], q1.y, qb.y));
                zg += fmaf(vv0[mi], q0.z, fmaf(vv1[mi], q1.z, qb.z));
                zo += fmaf(vv0[mi], q0.w, fmaf(vv1[mi], q1.w, qb.w));
                float ig = sigmoidf_(zi);
                float fg = sigmoidf_(zf);
                float gg = fmaxf(zg, 0.f);
                float og = sigmoidf_(zo);
                int gcol = qcol >> 2;
                size_t cidx = (size_t)row * NG + gcol;
                float cn = fmaf(fg, c_state[cidx], ig * gg);
                c_state[cidx] = cn;
                float h = og * fmaxf(cn, 0.f);
                __nv_bfloat16 hh = __float2bfloat16(h);
                __nv_bfloat16 hl = __float2bfloat16(h - __bfloat162float(hh));
                size_t ho = pk_off(row, gcol);
                *(__nv_bfloat16*)(hpk_out + ho)         = hh;
                *(__nv_bfloat16*)(hpk_out + ho + 16384) = hl;
                int hsrow = row * TT + t;
                size_t so = pk_off(hsrow, gcol);
                *(__nv_bfloat16*)(hspk_out + so)         = hh;
                *(__nv_bfloat16*)(hspk_out + so + 16384) = hl;
            }
    } else {
#pragma unroll
        for (int mi = 0; mi < 4; mi++)
#pragma unroll
            for (int ni = 0; ni < 4; ni++) {
                int row0 = m0 + wm * 64 + mi * 16 + gi;
                int col  = n0 + wn * 32 + ni * 8 + ci * 2;
                float bx = bias[col], by = bias[col + 1];
                float r0 = acc[mi][ni][0] + bx, r1 = acc[mi][ni][1] + by;
                float r2 = acc[mi][ni][2] + bx, r3 = acc[mi][ni][3] + by;
                if (MODE == 0) {
                    *(float2*)(Cout + (size_t)row0 * Nout + col)       = make_float2(r0, r1);
                    *(float2*)(Cout + (size_t)(row0 + 8) * Nout + col) = make_float2(r2, r3);
                } else {
                    r0 = fmaxf(r0, 0.f); r1 = fmaxf(r1, 0.f);
                    r2 = fmaxf(r2, 0.f); r3 = fmaxf(r3, 0.f);
                    __nv_bfloat16 h0 = __float2bfloat16(r0), h1 = __float2bfloat16(r1);
                    __nv_bfloat16 h2 = __float2bfloat16(r2), h3 = __float2bfloat16(r3);
                    size_t o0 = pk_off(row0, col);
                    size_t o1 = pk_off(row0 + 8, col);
                    *(__nv_bfloat162*)(gpk_out + o0) = __nv_bfloat162(h0, h1);
                    *(__nv_bfloat162*)(gpk_out + o1) = __nv_bfloat162(h2, h3);
                    *(__nv_bfloat162*)(gpk_out + o0 + 16384) = __nv_bfloat162(
                        __float2bfloat16(r0 - __bfloat162float(h0)),
                        __float2bfloat16(r1 - __bfloat162float(h1)));
                    *(__nv_bfloat162*)(gpk_out + o1 + 16384) = __nv_bfloat162(
                        __float2bfloat16(r2 - __bfloat162float(h2)),
                        __float2bfloat16(r3 - __bfloat162float(h3)));
                }
            }
    }
}

// ---------------------------------------------------------------------------
extern "C" void kernel_launch(void* const* d_in, const int* in_sizes, int n_in,
                              void* d_out, int out_size) {
    const float* v       = (const float*)d_in[0];
    const float* p0      = (const float*)d_in[1];
    const float* enc1_W  = (const float*)d_in[2];
    const float* enc1_b  = (const float*)d_in[3];
    const float* enc2_W  = (const float*)d_in[4];
    const float* enc2_b  = (const float*)d_in[5];
    const float* M_W     = (const float*)d_in[6];
    const float* M_b     = (const float*)d_in[7];
    const float* lstm_W  = (const float*)d_in[8];
    const float* lstm_U  = (const float*)d_in[9];
    const float* lstm_b  = (const float*)d_in[10];
    const float* dense_W = (const float*)d_in[11];
    const float* dense_b = (const float*)d_in[12];
    const float* dec_W   = (const float*)d_in[13];
    const float* dec_b   = (const float*)d_in[14];
    float* out = (float*)d_out;

    char *Upk, *DWpk, *DCpk, *hpk, *hspk, *gpk;
    float *cp;
    cudaGetSymbolAddress((void**)&Upk,  d_Upk);
    cudaGetSymbolAddress((void**)&DWpk, d_DWpk);
    cudaGetSymbolAddress((void**)&DCpk, d_DCpk);
    cudaGetSymbolAddress((void**)&hpk,  d_hpk);
    cudaGetSymbolAddress((void**)&hspk, d_hspk);
    cudaGetSymbolAddress((void**)&gpk,  d_gpk);
    cudaGetSymbolAddress((void**)&cp,   d_cbuf);

    const int SMEMSZ = 3 * 65536;  // 192 KB, 3-stage bulk pipeline
    cudaFuncSetAttribute(hmma_gemm<0>, cudaFuncAttributeMaxDynamicSharedMemorySize, SMEMSZ);
    cudaFuncSetAttribute(hmma_gemm<1>, cudaFuncAttributeMaxDynamicSharedMemorySize, SMEMSZ);
    cudaFuncSetAttribute(hmma_gemm<2>, cudaFuncAttributeMaxDynamicSharedMemorySize, SMEMSZ);

    // 1) Weight prep
    prep_w2_k<<<G4 / 256, 256>>>(lstm_W, lstm_b, M_W, M_b);
    transp_split_all<<<21504, dim3(32, 8)>>>(lstm_U, dense_W, dec_W);

    // 2) Initial state: h0 packed split bf16 + c0 fp32
    enc_k<<<dim3(NG / 64, BB / 128, 2), 256>>>(p0, enc1_W, enc1_b, enc2_W, enc2_b,
                                               hpk, cp);

    // 3) Recurrence: 100 HMMA steps, warp-specialized, barrier-free mainloop
    const size_t HP = (size_t)(BB / 128) * NCH * TILEB;
    for (int tstep = 0; tstep < TT; tstep++) {
        int pi = tstep & 1, po = (tstep + 1) & 1;
        hmma_gemm<2><<<dim3(G4 / 128, BB / 128), 288, SMEMSZ>>>(
            hpk + pi * HP, Upk, nullptr, nullptr, 0,
            v, cp, hpk + po * HP, hspk, nullptr, tstep);
    }

    // 4) dense: g = relu(hs @ dense_W + b) -> packed split bf16
    hmma_gemm<1><<<dim3(NG / 128, MTR / 128), 288, SMEMSZ>>>(
        hspk, DWpk, dense_b, nullptr, 0,
        nullptr, nullptr, nullptr, nullptr, gpk, 0);

    // 5) dec: out = g @ dec_W + b -> fp32
    hmma_gemm<0><<<dim3(NP / 128, MTR / 128), 288, SMEMSZ>>>(
        gpk, DCpk, dec_b, out, NP,
        nullptr, nullptr, nullptr, nullptr, nullptr, 0);
}

// round 10
// speedup vs baseline: 1.2579x; 1.0432x over previous
#include <cuda_runtime.h>
#include <cuda_bf16.h>
#include <cstdint>

// Problem constants
#define BB   256
#define TT   100
#define NG   2048
#define NP   512
#define G4   8192          // 4*NG
#define MTR  (BB * TT)     // 25600 rows for dense/dec stages
#define NCH  32            // K/64 chunks (K=2048 for all three big GEMMs)
#define ATB  32768         // packed A tile: 128 rows x 64 cols x 2B x (hi|lo)
#define BTB  16384         // packed B tile:  64 rows x 64 cols x 2B x (hi|lo)
#define STAGEB (ATB + BTB) // 48KB per pipeline stage

// ---------------------------------------------------------------------------
// Static device scratch — packed, pre-swizzled operand tiles
// A-side blobs: 128-row tiles. B-side blobs: 64-row tiles.
// ---------------------------------------------------------------------------
__device__ __align__(128) float d_W2pk[2 * G4];
__device__ __align__(128) float d_b2pk[G4];
__device__ __align__(128) char d_Upk [(size_t)(G4 / 64) * NCH * BTB];      // 64 MB
__device__ __align__(128) char d_DWpk[(size_t)(NG / 64) * NCH * BTB];      // 16 MB
__device__ __align__(128) char d_DCpk[(size_t)(NP / 64) * NCH * BTB];      // 4 MB
__device__ __align__(128) char d_hpk [2][(size_t)(BB / 128) * NCH * ATB];
__device__ __align__(128) float d_cbuf[(size_t)BB * NG];
__device__ __align__(128) char d_hspk[(size_t)(MTR / 128) * NCH * ATB];    // 200 MB
__device__ __align__(128) char d_gpk [(size_t)(MTR / 128) * NCH * ATB];    // 200 MB

__device__ __forceinline__ float sigmoidf_(float z) {
    return 1.0f / (1.0f + __expf(-z));
}

// ---------------------------------------------------------------------------
// PTX helpers
// ---------------------------------------------------------------------------
__device__ __forceinline__ uint32_t smem_u32(const void* p) {
    uint32_t a;
    asm("{ .reg .u64 t; cvta.to.shared.u64 t, %1; cvt.u32.u64 %0, t; }" : "=r"(a) : "l"(p));
    return a;
}
#define MBAR_INIT(addr, cnt) \
    asm volatile("mbarrier.init.shared.b64 [%0], %1;" :: "r"(addr), "r"((uint32_t)(cnt)) : "memory")
#define MBAR_EXPECT(addr, bytes) \
    asm volatile("mbarrier.arrive.expect_tx.shared.b64 _, [%0], %1;" :: "r"(addr), "r"((uint32_t)(bytes)) : "memory")
#define MBAR_ARRIVE(addr) \
    asm volatile("mbarrier.arrive.shared.b64 _, [%0];" :: "r"(addr) : "memory")
#define BULK_CP(dst, src, bytes, mbar) \
    asm volatile("cp.async.bulk.shared::cta.global.mbarrier::complete_tx::bytes [%0], [%1], %2, [%3];" \
        :: "r"(dst), "l"(src), "r"((uint32_t)(bytes)), "r"(mbar) : "memory")
#define MBAR_WAIT(addr, parity) do { \
    uint32_t _m = (addr); uint32_t _p = (parity); uint32_t _done; \
    asm volatile("{\n\t.reg .pred p;\n\t" \
        "mbarrier.try_wait.parity.acquire.cta.shared::cta.b64 p, [%1], %2;\n\t" \
        "selp.b32 %0, 1, 0, p;\n\t}" : "=r"(_done) : "r"(_m), "r"(_p) : "memory"); \
    if (!_done) { \
        asm volatile("{\n\t.reg .pred P1;\n\t" \
            "WL_%=:\n\t" \
            "mbarrier.try_wait.parity.acquire.cta.shared::cta.b64 P1, [%0], %1, 0x989680;\n\t" \
            "@P1 bra.uni WD_%=;\n\t" \
            "bra.uni WL_%=;\n\t" \
            "WD_%=:\n\t}" :: "r"(_m), "r"(_p) : "memory"); \
    } } while (0)

#define LDMX4(r0, r1, r2, r3, addr) \
    asm volatile("ldmatrix.sync.aligned.m8n8.x4.shared.b16 {%0,%1,%2,%3}, [%4];" \
        : "=r"(r0), "=r"(r1), "=r"(r2), "=r"(r3) : "r"(addr))

#define MMA16816(d, a, b0, b1) \
    asm("mma.sync.aligned.m16n8k16.row.col.f32.bf16.bf16.f32 " \
        "{%0,%1,%2,%3}, {%4,%5,%6,%7}, {%8,%9}, {%0,%1,%2,%3};" \
        : "+f"((d)[0]), "+f"((d)[1]), "+f"((d)[2]), "+f"((d)[3]) \
        : "r"((a)[0]), "r"((a)[1]), "r"((a)[2]), "r"((a)[3]), "r"(b0), "r"(b1))

// swizzled byte offset inside a [rows x 128B] tile
__device__ __forceinline__ uint32_t swz(int row, int colbyte) {
    return (uint32_t)((row << 7) + (colbyte ^ ((row & 7) << 4)));
}
// A-side packed blob offset: 128-row x 64-col tiles, [hi 16KB | lo 16KB]
__device__ __forceinline__ size_t pk_off(int row, int col) {
    return (size_t)((row >> 7) * NCH + (col >> 6)) * ATB + swz(row & 127, (col & 63) * 2);
}
// B-side packed blob offset: 64-row x 64-col tiles, [hi 8KB | lo 8KB]
__device__ __forceinline__ size_t pkb_off(int row, int col) {
    return (size_t)((row >> 6) * NCH + (col >> 6)) * BTB + swz(row & 63, (col & 63) * 2);
}

// ---------------------------------------------------------------------------
// prep: collapse v->gates (rank-2 trick), gate-interleaved; coalesced reads
// ---------------------------------------------------------------------------
__global__ void prep_w2_k(const float* __restrict__ lstm_W,
                          const float* __restrict__ lstm_b,
                          const float* __restrict__ M_W,
                          const float* __restrict__ M_b) {
    int j = blockIdx.x * blockDim.x + threadIdx.x;
    if (j >= G4) return;
    float w0 = 0.f, w1 = 0.f, bb = 0.f;
#pragma unroll 8
    for (int g = 0; g < NG; g++) {
        float lw = lstm_W[(size_t)g * G4 + j];
        w0 = fmaf(M_W[g],      lw, w0);
        w1 = fmaf(M_W[NG + g], lw, w1);
        bb = fmaf(M_b[g],      lw, bb);
    }
    int n = (j & (NG - 1)) * 4 + (j >> 11);
    d_W2pk[n]      = w0;
    d_W2pk[G4 + n] = w1;
    d_b2pk[n]      = bb + lstm_b[j];
}

// ---------------------------------------------------------------------------
// Fused transpose+split+pack for U (gate-interleaved), dense_W, dec_W.
// Writes B-side packed blobs (64-row tiles).
// ---------------------------------------------------------------------------
__global__ void transp_split_all(const float* __restrict__ U,
                                 const float* __restrict__ DW,
                                 const float* __restrict__ DC) {
    __shared__ float tile[32][33];
    int bid = blockIdx.x;
    const float* src;
    char* pk;
    int N, bx, by;
    bool gate = false;
    if (bid < 16384) {
        src = U;  pk = d_Upk;  N = G4; gate = true;
        bx = bid & 63; by = bid >> 6;
    } else if (bid < 20480) {
        int l = bid - 16384;
        src = DW; pk = d_DWpk; N = NG;
        bx = l & 63; by = l >> 6;
    } else {
        int l = bid - 20480;
        src = DC; pk = d_DCpk; N = NP;
        bx = l & 63; by = l >> 6;
    }
    int k0 = bx * 32, j0 = by * 32;
    int tx = threadIdx.x, ty = threadIdx.y;   // (32, 8)
#pragma unroll
    for (int i = 0; i < 4; i++)
        tile[ty + i * 8][tx] = src[(size_t)(k0 + ty + i * 8) * N + j0 + tx];
    __syncthreads();
#pragma unroll
    for (int i = 0; i < 4; i++) {
        int j = j0 + ty + i * 8;
        int n = gate ? ((j & (NG - 1)) * 4 + (j >> 11)) : j;
        int k = k0 + tx;
        float x = tile[tx][ty + i * 8];       // src[k][j]
        __nv_bfloat16 h = __float2bfloat16(x);
        size_t off = pkb_off(n, k);
        *(__nv_bfloat16*)(pk + off)        = h;
        *(__nv_bfloat16*)(pk + off + 8192) = __float2bfloat16(x - __bfloat162float(h));
    }
}

// ---------------------------------------------------------------------------
// Fused encoder: z=0 -> h0 = p0@enc1_W+b (packed split bf16); z=1 -> c0 fp32
// ---------------------------------------------------------------------------
__global__ __launch_bounds__(256)
void enc_k(const float* __restrict__ p0,
           const float* __restrict__ W1, const float* __restrict__ b1,
           const float* __restrict__ W2, const float* __restrict__ b2,
           char* __restrict__ hpk0, float* __restrict__ c0) {
    __shared__ float As[16][132];
    __shared__ float Bs[16][64];
    const int z = blockIdx.z;
    const float* A = p0;
    const float* W = z ? W2 : W1;
    const float* bias = z ? b2 : b1;
    const int N = NG, K = NP;
    const int tid = threadIdx.x;
    const int tx = tid & 15;
    const int ty = tid >> 4;
    const int m0 = blockIdx.y * 128;
    const int n0 = blockIdx.x * 64;

    float acc[8][4];
#pragma unroll
    for (int i = 0; i < 8; i++)
#pragma unroll
        for (int j = 0; j < 4; j++) acc[i][j] = 0.f;

    for (int k0 = 0; k0 < K; k0 += 16) {
#pragma unroll
        for (int it = 0; it < 2; it++) {
            int fid = tid + it * 256;
            int m = fid >> 2;
            int kq = (fid & 3) << 2;
            float4 a4 = *(const float4*)(A + (size_t)(m0 + m) * K + k0 + kq);
            As[kq + 0][m] = a4.x; As[kq + 1][m] = a4.y;
            As[kq + 2][m] = a4.z; As[kq + 3][m] = a4.w;
        }
        {
            int kk = tid >> 4;
            int n4 = (tid & 15) << 2;
            *(float4*)&Bs[kk][n4] = *(const float4*)(W + (size_t)(k0 + kk) * N + n0 + n4);
        }
        __syncthreads();
#pragma unroll
        for (int k = 0; k < 16; k++) {
            float a[8], b[4];
            *(float4*)(a)     = *(const float4*)&As[k][ty * 4];
            *(float4*)(a + 4) = *(const float4*)&As[k][64 + ty * 4];
            *(float4*)(b)     = *(const float4*)&Bs[k][tx * 4];
#pragma unroll
            for (int i = 0; i < 8; i++)
#pragma unroll
                for (int j = 0; j < 4; j++)
                    acc[i][j] = fmaf(a[i], b[j], acc[i][j]);
        }
        __syncthreads();
    }

    float4 b4 = *(const float4*)&bias[n0 + tx * 4];
#pragma unroll
    for (int i = 0; i < 8; i++) {
        int m_ = m0 + ((i < 4) ? (ty * 4 + i) : (64 + ty * 4 + i - 4));
#pragma unroll
        for (int j = 0; j < 4; j++) {
            float r = acc[i][j] + ((j == 0) ? b4.x : (j == 1) ? b4.y : (j == 2) ? b4.z : b4.w);
            int col = n0 + tx * 4 + j;
            if (z) {
                c0[(size_t)m_ * NG + col] = r;
            } else {
                __nv_bfloat16 h = __float2bfloat16(r);
                size_t off = pk_off(m_, col);
                *(__nv_bfloat16*)(hpk0 + off)         = h;
                *(__nv_bfloat16*)(hpk0 + off + 16384) = __float2bfloat16(r - __bfloat162float(h));
            }
        }
    }
}

// ---------------------------------------------------------------------------
// Fragment load/compute macros.
// Stage layout: A hi @0 (16KB) | A lo @16K | B hi @32K (8KB) | B lo @40960
// ---------------------------------------------------------------------------
#define LOAD_FRAGS(S, KK) \
    { \
        _Pragma("unroll") \
        for (int mi = 0; mi < 4; mi++) { \
            uint32_t off = swz(wm * 64 + mi * 16 + a_r, (KK) * 32 + a_cb); \
            LDMX4(ah[S][mi][0], ah[S][mi][1], ah[S][mi][2], ah[S][mi][3], stg + off); \
            LDMX4(al[S][mi][0], al[S][mi][1], al[S][mi][2], al[S][mi][3], stg + 16384u + off); \
        } \
        _Pragma("unroll") \
        for (int bt = 0; bt < 2; bt++) { \
            uint32_t off = swz(wn * 32 + bt * 16 + b_r, (KK) * 32 + b_cb); \
            LDMX4(bh[S][bt][0], bh[S][bt][1], bh[S][bt][2], bh[S][bt][3], stg + 32768u + off); \
            LDMX4(bl[S][bt][0], bl[S][bt][1], bl[S][bt][2], bl[S][bt][3], stg + 40960u + off); \
        } \
    }

#define MMA_ALL(S) \
    { \
        _Pragma("unroll") \
        for (int mi = 0; mi < 4; mi++) \
        _Pragma("unroll") \
        for (int ni = 0; ni < 4; ni++) { \
            int bt = ni >> 1, pr = (ni & 1) * 2; \
            MMA16816(acc[mi][ni], ah[S][mi], bh[S][bt][pr], bh[S][bt][pr + 1]); \
        } \
        _Pragma("unroll") \
        for (int mi = 0; mi < 4; mi++) \
        _Pragma("unroll") \
        for (int ni = 0; ni < 4; ni++) { \
            int bt = ni >> 1, pr = (ni & 1) * 2; \
            MMA16816(acc[mi][ni], ah[S][mi], bl[S][bt][pr], bl[S][bt][pr + 1]); \
        } \
        _Pragma("unroll") \
        for (int mi = 0; mi < 4; mi++) \
        _Pragma("unroll") \
        for (int ni = 0; ni < 4; ni++) { \
            int bt = ni >> 1, pr = (ni & 1) * 2; \
            MMA16816(acc[mi][ni], al[S][mi], bh[S][bt][pr], bh[S][bt][pr + 1]); \
        } \
    }

// ---------------------------------------------------------------------------
// HMMA split-bf16 GEMM: 2 CTAs/SM for independent-pipeline interleaving.
// CTA tile 128(m) x 64(n); 160 threads = 4 compute warps (2m x 2n, 64x32
// warp tiles) + 1 producer warp. 2-stage 96KB ring, warp-specialized,
// no CTA-wide barriers in the mainloop.
// MODE 0: fp32 bias out (dec). MODE 1: relu+bias -> packed g (dense).
// MODE 2: fused LSTM gate epilogue -> packed h + packed hs.
// ---------------------------------------------------------------------------
template <int MODE>
__global__ __launch_bounds__(160, 2)
void hmma_gemm(const char* __restrict__ Apk, const char* __restrict__ Bpk,
               const float* __restrict__ bias, float* __restrict__ Cout,
               int Nout,
               const float* __restrict__ v, float* __restrict__ c_state,
               char* __restrict__ hpk_out, char* __restrict__ hspk_out,
               char* __restrict__ gpk_out,
               int t) {
    extern __shared__ char smem[];
    __shared__ __align__(8) uint64_t mbars[4];   // full[0..1], empty[0..1]
    const uint32_t sb = smem_u32(smem);
    const int tid  = threadIdx.x;
    const int lane = tid & 31;
    const int wid  = tid >> 5;          // 0..4
    const int n0 = blockIdx.x * 64;
    const int m0 = blockIdx.y * 128;
    const int NC = NCH;

    const char* Abase = Apk + (size_t)(m0 >> 7) * NCH * ATB;
    const char* Bbase = Bpk + (size_t)(n0 >> 6) * NCH * BTB;

    if (tid == 0) {
#pragma unroll
        for (int i = 0; i < 2; i++) {
            MBAR_INIT(smem_u32(&mbars[i]), 1);       // full: 1 tx-completion
            MBAR_INIT(smem_u32(&mbars[2 + i]), 4);   // empty: 4 warp arrivals
        }
    }
    __syncthreads();

    if (wid == 4) {
        // ---- producer warp ----
        if (lane == 0) {
            for (int c = 0; c < NC; c++) {
                int i = c & 1;
                if (c >= 2) MBAR_WAIT(smem_u32(&mbars[2 + i]), ((c >> 1) - 1) & 1);
                uint32_t mb = smem_u32(&mbars[i]);
                MBAR_EXPECT(mb, STAGEB);
                uint32_t dst = sb + (uint32_t)i * STAGEB;
                BULK_CP(dst,          Abase + (size_t)c * ATB, ATB, mb);
                BULK_CP(dst + 32768u, Bbase + (size_t)c * BTB, BTB, mb);
            }
        }
        return;
    }

    // ---- compute warps ----
    const int wm = wid >> 1;            // 0..1
    const int wn = wid & 1;             // 0..1
    const int a_r  = (lane & 7) + ((lane >> 3) & 1) * 8;
    const int a_cb = ((lane >> 4) & 1) * 16;
    const int b_r  = (lane & 7) + ((lane >> 4) & 1) * 8;
    const int b_cb = ((lane >> 3) & 1) * 16;

    float acc[4][4][4];
#pragma unroll
    for (int i = 0; i < 4; i++)
#pragma unroll
        for (int j = 0; j < 4; j++)
#pragma unroll
            for (int r = 0; r < 4; r++) acc[i][j][r] = 0.f;

    int buf = 0;
    for (int it = 0; it < NC; it++) {
        MBAR_WAIT(smem_u32(&mbars[buf]), (it >> 1) & 1);
        uint32_t stg = sb + (uint32_t)buf * STAGEB;

        uint32_t ah[2][4][4], al[2][4][4], bh[2][2][4], bl[2][2][4];
        LOAD_FRAGS(0, 0);
        LOAD_FRAGS(1, 1); MMA_ALL(0);
        LOAD_FRAGS(0, 2); MMA_ALL(1);
        LOAD_FRAGS(1, 3); MMA_ALL(0);
        MMA_ALL(1);

        __syncwarp();
        if (lane == 0) MBAR_ARRIVE(smem_u32(&mbars[2 + buf]));
        buf ^= 1;
    }

    // ---- Epilogue ----
    const int gi = lane >> 2;
    const int ci = lane & 3;

    if (MODE == 2) {
        const bool isIF = (lane & 1) == 0;
        int rowm[4];
        float vv0[4], vv1[4];
#pragma unroll
        for (int mi = 0; mi < 4; mi++) {
            rowm[mi] = m0 + wm * 64 + mi * 16 + gi + (isIF ? 0 : 8);
            size_t vr = ((size_t)rowm[mi] * TT + t) * 2;
            vv0[mi] = v[vr];
            vv1[mi] = v[vr + 1];
        }
#pragma unroll
        for (int mi = 0; mi < 4; mi++)
#pragma unroll
            for (int ni = 0; ni < 4; ni++) {
                float c0 = acc[mi][ni][0], c1 = acc[mi][ni][1];
                float c2 = acc[mi][ni][2], c3 = acc[mi][ni][3];
                float o0 = __shfl_xor_sync(0xFFFFFFFFu, c0, 1);
                float o1 = __shfl_xor_sync(0xFFFFFFFFu, c1, 1);
                float o2 = __shfl_xor_sync(0xFFFFFFFFu, c2, 1);
                float o3 = __shfl_xor_sync(0xFFFFFFFFu, c3, 1);
                float zi = isIF ? c0 : o2;
                float zf = isIF ? c1 : o3;
                float zg = isIF ? o0 : c2;
                float zo = isIF ? o1 : c3;
                int row  = rowm[mi];
                int qcol = n0 + wn * 32 + ni * 8 + (ci >> 1) * 4;
                float4 q0 = *(const float4*)&d_W2pk[qcol];
                float4 q1 = *(const float4*)&d_W2pk[G4 + qcol];
                float4 qb = *(const float4*)&d_b2pk[qcol];
                zi += fmaf(vv0[mi], q0.x, fmaf(vv1[mi], q1.x, qb.x));
                zf += fmaf(vv0[mi], q0.y, fmaf(vv1[mi], q1.y, qb.y));
                zg += fmaf(vv0[mi], q0.z, fmaf(vv1[mi], q1.z, qb.z));
                zo += fmaf(vv0[mi], q0.w, fmaf(vv1[mi], q1.w, qb.w));
                float ig = sigmoidf_(zi);
                float fg = sigmoidf_(zf);
                float gg = fmaxf(zg, 0.f);
                float og = sigmoidf_(zo);
                int gcol = qcol >> 2;
                size_t cidx = (size_t)row * NG + gcol;
                float cn = fmaf(fg, c_state[cidx], ig * gg);
                c_state[cidx] = cn;
                float h = og * fmaxf(cn, 0.f);
                __nv_bfloat16 hh = __float2bfloat16(h);
                __nv_bfloat16 hl = __float2bfloat16(h - __bfloat162float(hh));
                size_t ho = pk_off(row, gcol);
                *(__nv_bfloat16*)(hpk_out + ho)         = hh;
                *(__nv_bfloat16*)(hpk_out + ho + 16384) = hl;
                int hsrow = row * TT + t;
                size_t so = pk_off(hsrow, gcol);
                *(__nv_bfloat16*)(hspk_out + so)         = hh;
                *(__nv_bfloat16*)(hspk_out + so + 16384) = hl;
            }
    } else {
#pragma unroll
        for (int mi = 0; mi < 4; mi++)
#pragma unroll
            for (int ni = 0; ni < 4; ni++) {
                int row0 = m0 + wm * 64 + mi * 16 + gi;
                int col  = n0 + wn * 32 + ni * 8 + ci * 2;
                float bx = bias[col], by = bias[col + 1];
                float r0 = acc[mi][ni][0] + bx, r1 = acc[mi][ni][1] + by;
                float r2 = acc[mi][ni][2] + bx, r3 = acc[mi][ni][3] + by;
                if (MODE == 0) {
                    *(float2*)(Cout + (size_t)row0 * Nout + col)       = make_float2(r0, r1);
                    *(float2*)(Cout + (size_t)(row0 + 8) * Nout + col) = make_float2(r2, r3);
                } else {
                    r0 = fmaxf(r0, 0.f); r1 = fmaxf(r1, 0.f);
                    r2 = fmaxf(r2, 0.f); r3 = fmaxf(r3, 0.f);
                    __nv_bfloat16 h0 = __float2bfloat16(r0), h1 = __float2bfloat16(r1);
                    __nv_bfloat16 h2 = __float2bfloat16(r2), h3 = __float2bfloat16(r3);
                    size_t o0 = pk_off(row0, col);
                    size_t o1 = pk_off(row0 + 8, col);
                    *(__nv_bfloat162*)(gpk_out + o0) = __nv_bfloat162(h0, h1);
                    *(__nv_bfloat162*)(gpk_out + o1) = __nv_bfloat162(h2, h3);
                    *(__nv_bfloat162*)(gpk_out + o0 + 16384) = __nv_bfloat162(
                        __float2bfloat16(r0 - __bfloat162float(h0)),
                        __float2bfloat16(r1 - __bfloat162float(h1)));
                    *(__nv_bfloat162*)(gpk_out + o1 + 16384) = __nv_bfloat162(
                        __float2bfloat16(r2 - __bfloat162float(h2)),
                        __float2bfloat16(r3 - __bfloat162float(h3)));
                }
            }
    }
}

// ---------------------------------------------------------------------------
extern "C" void kernel_launch(void* const* d_in, const int* in_sizes, int n_in,
                              void* d_out, int out_size) {
    const float* v       = (const float*)d_in[0];
    const float* p0      = (const float*)d_in[1];
    const float* enc1_W  = (const float*)d_in[2];
    const float* enc1_b  = (const float*)d_in[3];
    const float* enc2_W  = (const float*)d_in[4];
    const float* enc2_b  = (const float*)d_in[5];
    const float* M_W     = (const float*)d_in[6];
    const float* M_b     = (const float*)d_in[7];
    const float* lstm_W  = (const float*)d_in[8];
    const float* lstm_U  = (const float*)d_in[9];
    const float* lstm_b  = (const float*)d_in[10];
    const float* dense_W = (const float*)d_in[11];
    const float* dense_b = (const float*)d_in[12];
    const float* dec_W   = (const float*)d_in[13];
    const float* dec_b   = (const float*)d_in[14];
    float* out = (float*)d_out;

    char *Upk, *DWpk, *DCpk, *hpk, *hspk, *gpk;
    float *cp;
    cudaGetSymbolAddress((void**)&Upk,  d_Upk);
    cudaGetSymbolAddress((void**)&DWpk, d_DWpk);
    cudaGetSymbolAddress((void**)&DCpk, d_DCpk);
    cudaGetSymbolAddress((void**)&hpk,  d_hpk);
    cudaGetSymbolAddress((void**)&hspk, d_hspk);
    cudaGetSymbolAddress((void**)&gpk,  d_gpk);
    cudaGetSymbolAddress((void**)&cp,   d_cbuf);

    const int SMEMSZ = 2 * STAGEB;  // 96 KB -> 2 CTAs/SM
    cudaFuncSetAttribute(hmma_gemm<0>, cudaFuncAttributeMaxDynamicSharedMemorySize, SMEMSZ);
    cudaFuncSetAttribute(hmma_gemm<1>, cudaFuncAttributeMaxDynamicSharedMemorySize, SMEMSZ);
    cudaFuncSetAttribute(hmma_gemm<2>, cudaFuncAttributeMaxDynamicSharedMemorySize, SMEMSZ);

    // 1) Weight prep
    prep_w2_k<<<G4 / 256, 256>>>(lstm_W, lstm_b, M_W, M_b);
    transp_split_all<<<21504, dim3(32, 8)>>>(lstm_U, dense_W, dec_W);

    // 2) Initial state: h0 packed split bf16 + c0 fp32
    enc_k<<<dim3(NG / 64, BB / 128, 2), 256>>>(p0, enc1_W, enc1_b, enc2_W, enc2_b,
                                               hpk, cp);

    // 3) Recurrence: 100 HMMA steps, 2 CTAs/SM, warp-specialized
    const size_t HP = (size_t)(BB / 128) * NCH * ATB;
    for (int tstep = 0; tstep < TT; tstep++) {
        int pi = tstep & 1, po = (tstep + 1) & 1;
        hmma_gemm<2><<<dim3(G4 / 64, BB / 128), 160, SMEMSZ>>>(
            hpk + pi * HP, Upk, nullptr, nullptr, 0,
            v, cp, hpk + po * HP, hspk, nullptr, tstep);
    }

    // 4) dense: g = relu(hs @ dense_W + b) -> packed split bf16
    hmma_gemm<1><<<dim3(NG / 64, MTR / 128), 160, SMEMSZ>>>(
        hspk, DWpk, dense_b, nullptr, 0,
        nullptr, nullptr, nullptr, nullptr, gpk, 0);

    // 5) dec: out = g @ dec_W + b -> fp32
    hmma_gemm<0><<<dim3(NP / 64, MTR / 128), 160, SMEMSZ>>>(
        gpk, DCpk, dec_b, out, NP,
        nullptr, nullptr, nullptr, nullptr, nullptr, 0);
}

// round 11
// speedup vs baseline: 1.5940x; 1.2672x over previous
#include <cuda_runtime.h>
#include <cuda_fp16.h>
#include <cstdint>

// Problem constants
#define BB   256
#define TT   100
#define NG   2048
#define NP   512
#define G4   8192          // 4*NG
#define MTR  (BB * TT)     // 25600 rows for dense/dec stages
#define NCH  32            // K/64 chunks (K=2048 for all three big GEMMs)
#define ATB  32768         // packed A tile: 128 rows x 64 cols x 2B x (hi|lo)
#define BTB  8192          // packed B tile:  64 rows x 64 cols x 2B (single fp16)
#define STAGEB (ATB + BTB) // 40960 bytes per pipeline stage

// ---------------------------------------------------------------------------
// Static device scratch — packed, pre-swizzled operand tiles
// A-side blobs: 128-row split-fp16 [hi 16K | lo 16K] tiles.
// B-side blobs: 64-row single-fp16 8KB tiles.
// ---------------------------------------------------------------------------
__device__ __align__(128) float d_W2pk[2 * G4];
__device__ __align__(128) float d_b2pk[G4];
__device__ __align__(128) char d_Upk [(size_t)(G4 / 64) * NCH * BTB];      // 32 MB
__device__ __align__(128) char d_DWpk[(size_t)(NG / 64) * NCH * BTB];      // 8 MB
__device__ __align__(128) char d_DCpk[(size_t)(NP / 64) * NCH * BTB];      // 2 MB
__device__ __align__(128) char d_hpk [2][(size_t)(BB / 128) * NCH * ATB];  // 2x2 MB
__device__ __align__(128) float d_cbuf[(size_t)BB * NG];
__device__ __align__(128) char d_hspk[(size_t)(MTR / 128) * NCH * ATB];    // 200 MB
__device__ __align__(128) char d_gpk [(size_t)(MTR / 128) * NCH * ATB];    // 200 MB

__device__ __forceinline__ float sigmoidf_(float z) {
    return 1.0f / (1.0f + __expf(-z));
}

// ---------------------------------------------------------------------------
// PTX helpers
// ---------------------------------------------------------------------------
__device__ __forceinline__ uint32_t smem_u32(const void* p) {
    uint32_t a;
    asm("{ .reg .u64 t; cvta.to.shared.u64 t, %1; cvt.u32.u64 %0, t; }" : "=r"(a) : "l"(p));
    return a;
}
#define MBAR_INIT(addr, cnt) \
    asm volatile("mbarrier.init.shared.b64 [%0], %1;" :: "r"(addr), "r"((uint32_t)(cnt)) : "memory")
#define MBAR_EXPECT(addr, bytes) \
    asm volatile("mbarrier.arrive.expect_tx.shared.b64 _, [%0], %1;" :: "r"(addr), "r"((uint32_t)(bytes)) : "memory")
#define MBAR_ARRIVE(addr) \
    asm volatile("mbarrier.arrive.shared.b64 _, [%0];" :: "r"(addr) : "memory")
#define BULK_CP(dst, src, bytes, mbar) \
    asm volatile("cp.async.bulk.shared::cta.global.mbarrier::complete_tx::bytes [%0], [%1], %2, [%3];" \
        :: "r"(dst), "l"(src), "r"((uint32_t)(bytes)), "r"(mbar) : "memory")
#define MBAR_WAIT(addr, parity) do { \
    uint32_t _m = (addr); uint32_t _p = (parity); uint32_t _done; \
    asm volatile("{\n\t.reg .pred p;\n\t" \
        "mbarrier.try_wait.parity.acquire.cta.shared::cta.b64 p, [%1], %2;\n\t" \
        "selp.b32 %0, 1, 0, p;\n\t}" : "=r"(_done) : "r"(_m), "r"(_p) : "memory"); \
    if (!_done) { \
        asm volatile("{\n\t.reg .pred P1;\n\t" \
            "WL_%=:\n\t" \
            "mbarrier.try_wait.parity.acquire.cta.shared::cta.b64 P1, [%0], %1, 0x989680;\n\t" \
            "@P1 bra.uni WD_%=;\n\t" \
            "bra.uni WL_%=;\n\t" \
            "WD_%=:\n\t}" :: "r"(_m), "r"(_p) : "memory"); \
    } } while (0)

#define LDMX4(r0, r1, r2, r3, addr) \
    asm volatile("ldmatrix.sync.aligned.m8n8.x4.shared.b16 {%0,%1,%2,%3}, [%4];" \
        : "=r"(r0), "=r"(r1), "=r"(r2), "=r"(r3) : "r"(addr))

#define MMAF16(d, a, b0, b1) \
    asm("mma.sync.aligned.m16n8k16.row.col.f32.f16.f16.f32 " \
        "{%0,%1,%2,%3}, {%4,%5,%6,%7}, {%8,%9}, {%0,%1,%2,%3};" \
        : "+f"((d)[0]), "+f"((d)[1]), "+f"((d)[2]), "+f"((d)[3]) \
        : "r"((a)[0]), "r"((a)[1]), "r"((a)[2]), "r"((a)[3]), "r"(b0), "r"(b1))

// swizzled byte offset inside a [rows x 128B] tile
__device__ __forceinline__ uint32_t swz(int row, int colbyte) {
    return (uint32_t)((row << 7) + (colbyte ^ ((row & 7) << 4)));
}
// A-side packed blob offset: 128-row x 64-col tiles, [hi 16KB | lo 16KB]
__device__ __forceinline__ size_t pk_off(int row, int col) {
    return (size_t)((row >> 7) * NCH + (col >> 6)) * ATB + swz(row & 127, (col & 63) * 2);
}
// B-side packed blob offset: 64-row x 64-col single-fp16 tiles (8KB)
__device__ __forceinline__ size_t pkb_off(int row, int col) {
    return (size_t)((row >> 6) * NCH + (col >> 6)) * BTB + swz(row & 63, (col & 63) * 2);
}

// ---------------------------------------------------------------------------
// prep: collapse v->gates (rank-2 trick), gate-interleaved; coalesced reads
// ---------------------------------------------------------------------------
__global__ void prep_w2_k(const float* __restrict__ lstm_W,
                          const float* __restrict__ lstm_b,
                          const float* __restrict__ M_W,
                          const float* __restrict__ M_b) {
    int j = blockIdx.x * blockDim.x + threadIdx.x;
    if (j >= G4) return;
    float w0 = 0.f, w1 = 0.f, bb = 0.f;
#pragma unroll 8
    for (int g = 0; g < NG; g++) {
        float lw = lstm_W[(size_t)g * G4 + j];
        w0 = fmaf(M_W[g],      lw, w0);
        w1 = fmaf(M_W[NG + g], lw, w1);
        bb = fmaf(M_b[g],      lw, bb);
    }
    int n = (j & (NG - 1)) * 4 + (j >> 11);
    d_W2pk[n]      = w0;
    d_W2pk[G4 + n] = w1;
    d_b2pk[n]      = bb + lstm_b[j];
}

// ---------------------------------------------------------------------------
// Fused transpose+pack for U (gate-interleaved), dense_W, dec_W.
// B-side: single fp16, 64-row 8KB tiles.
// ---------------------------------------------------------------------------
__global__ void transp_split_all(const float* __restrict__ U,
                                 const float* __restrict__ DW,
                                 const float* __restrict__ DC) {
    __shared__ float tile[32][33];
    int bid = blockIdx.x;
    const float* src;
    char* pk;
    int N, bx, by;
    bool gate = false;
    if (bid < 16384) {
        src = U;  pk = d_Upk;  N = G4; gate = true;
        bx = bid & 63; by = bid >> 6;
    } else if (bid < 20480) {
        int l = bid - 16384;
        src = DW; pk = d_DWpk; N = NG;
        bx = l & 63; by = l >> 6;
    } else {
        int l = bid - 20480;
        src = DC; pk = d_DCpk; N = NP;
        bx = l & 63; by = l >> 6;
    }
    int k0 = bx * 32, j0 = by * 32;
    int tx = threadIdx.x, ty = threadIdx.y;   // (32, 8)
#pragma unroll
    for (int i = 0; i < 4; i++)
        tile[ty + i * 8][tx] = src[(size_t)(k0 + ty + i * 8) * N + j0 + tx];
    __syncthreads();
#pragma unroll
    for (int i = 0; i < 4; i++) {
        int j = j0 + ty + i * 8;
        int n = gate ? ((j & (NG - 1)) * 4 + (j >> 11)) : j;
        int k = k0 + tx;
        float x = tile[tx][ty + i * 8];       // src[k][j]
        *(__half*)(pk + pkb_off(n, k)) = __float2half(x);
    }
}

// ---------------------------------------------------------------------------
// Fused encoder: z=0 -> h0 = p0@enc1_W+b (packed split fp16); z=1 -> c0 fp32
// ---------------------------------------------------------------------------
__global__ __launch_bounds__(256)
void enc_k(const float* __restrict__ p0,
           const float* __restrict__ W1, const float* __restrict__ b1,
           const float* __restrict__ W2, const float* __restrict__ b2,
           char* __restrict__ hpk0, float* __restrict__ c0) {
    __shared__ float As[16][132];
    __shared__ float Bs[16][64];
    const int z = blockIdx.z;
    const float* A = p0;
    const float* W = z ? W2 : W1;
    const float* bias = z ? b2 : b1;
    const int N = NG, K = NP;
    const int tid = threadIdx.x;
    const int tx = tid & 15;
    const int ty = tid >> 4;
    const int m0 = blockIdx.y * 128;
    const int n0 = blockIdx.x * 64;

    float acc[8][4];
#pragma unroll
    for (int i = 0; i < 8; i++)
#pragma unroll
        for (int j = 0; j < 4; j++) acc[i][j] = 0.f;

    for (int k0 = 0; k0 < K; k0 += 16) {
#pragma unroll
        for (int it = 0; it < 2; it++) {
            int fid = tid + it * 256;
            int m = fid >> 2;
            int kq = (fid & 3) << 2;
            float4 a4 = *(const float4*)(A + (size_t)(m0 + m) * K + k0 + kq);
            As[kq + 0][m] = a4.x; As[kq + 1][m] = a4.y;
            As[kq + 2][m] = a4.z; As[kq + 3][m] = a4.w;
        }
        {
            int kk = tid >> 4;
            int n4 = (tid & 15) << 2;
            *(float4*)&Bs[kk][n4] = *(const float4*)(W + (size_t)(k0 + kk) * N + n0 + n4);
        }
        __syncthreads();
#pragma unroll
        for (int k = 0; k < 16; k++) {
            float a[8], b[4];
            *(float4*)(a)     = *(const float4*)&As[k][ty * 4];
            *(float4*)(a + 4) = *(const float4*)&As[k][64 + ty * 4];
            *(float4*)(b)     = *(const float4*)&Bs[k][tx * 4];
#pragma unroll
            for (int i = 0; i < 8; i++)
#pragma unroll
                for (int j = 0; j < 4; j++)
                    acc[i][j] = fmaf(a[i], b[j], acc[i][j]);
        }
        __syncthreads();
    }

    float4 b4 = *(const float4*)&bias[n0 + tx * 4];
#pragma unroll
    for (int i = 0; i < 8; i++) {
        int m_ = m0 + ((i < 4) ? (ty * 4 + i) : (64 + ty * 4 + i - 4));
#pragma unroll
        for (int j = 0; j < 4; j++) {
            float r = acc[i][j] + ((j == 0) ? b4.x : (j == 1) ? b4.y : (j == 2) ? b4.z : b4.w);
            int col = n0 + tx * 4 + j;
            if (z) {
                c0[(size_t)m_ * NG + col] = r;
            } else {
                __half h = __float2half(r);
                size_t off = pk_off(m_, col);
                *(__half*)(hpk0 + off)         = h;
                *(__half*)(hpk0 + off + 16384) = __float2half(r - __half2float(h));
            }
        }
    }
}

// ---------------------------------------------------------------------------
// Fragment load/compute macros.
// Stage layout: A hi @0 (16KB) | A lo @16K (16KB) | B @32K (8KB)
// ---------------------------------------------------------------------------
#define LOAD_FRAGS(S, KK) \
    { \
        _Pragma("unroll") \
        for (int mi = 0; mi < 4; mi++) { \
            uint32_t off = swz(wm * 64 + mi * 16 + a_r, (KK) * 32 + a_cb); \
            LDMX4(ah[S][mi][0], ah[S][mi][1], ah[S][mi][2], ah[S][mi][3], stg + off); \
            LDMX4(al[S][mi][0], al[S][mi][1], al[S][mi][2], al[S][mi][3], stg + 16384u + off); \
        } \
        _Pragma("unroll") \
        for (int bt = 0; bt < 2; bt++) { \
            uint32_t off = swz(wn * 32 + bt * 16 + b_r, (KK) * 32 + b_cb); \
            LDMX4(bf[S][bt][0], bf[S][bt][1], bf[S][bt][2], bf[S][bt][3], stg + 32768u + off); \
        } \
    }

#define MMA_ALL(S) \
    { \
        _Pragma("unroll") \
        for (int mi = 0; mi < 4; mi++) \
        _Pragma("unroll") \
        for (int ni = 0; ni < 4; ni++) { \
            int bt = ni >> 1, pr = (ni & 1) * 2; \
            MMAF16(acc[mi][ni], ah[S][mi], bf[S][bt][pr], bf[S][bt][pr + 1]); \
        } \
        _Pragma("unroll") \
        for (int mi = 0; mi < 4; mi++) \
        _Pragma("unroll") \
        for (int ni = 0; ni < 4; ni++) { \
            int bt = ni >> 1, pr = (ni & 1) * 2; \
            MMAF16(acc[mi][ni], al[S][mi], bf[S][bt][pr], bf[S][bt][pr + 1]); \
        } \
    }

// ---------------------------------------------------------------------------
// HMMA split-fp16 GEMM: 2 CTAs/SM, warp-specialized, 2-product precision
// (A = hi+lo fp16, B = single fp16): 33% fewer MMAs than split-bf16 x3.
// CTA tile 128(m) x 64(n); 160 threads = 4 compute warps (2m x 2n, 64x32
// warp tiles) + 1 producer warp. 2-stage 80KB ring, no CTA-wide barriers.
// MODE 0: fp32 bias out (dec). MODE 1: relu+bias -> packed g (dense).
// MODE 2: fused LSTM gate epilogue -> packed h + packed hs.
// ---------------------------------------------------------------------------
template <int MODE>
__global__ __launch_bounds__(160, 2)
void hmma_gemm(const char* __restrict__ Apk, const char* __restrict__ Bpk,
               const float* __restrict__ bias, float* __restrict__ Cout,
               int Nout,
               const float* __restrict__ v, float* __restrict__ c_state,
               char* __restrict__ hpk_out, char* __restrict__ hspk_out,
               char* __restrict__ gpk_out,
               int t) {
    extern __shared__ char smem[];
    __shared__ __align__(8) uint64_t mbars[4];   // full[0..1], empty[0..1]
    const uint32_t sb = smem_u32(smem);
    const int tid  = threadIdx.x;
    const int lane = tid & 31;
    const int wid  = tid >> 5;          // 0..4
    const int n0 = blockIdx.x * 64;
    const int m0 = blockIdx.y * 128;
    const int NC = NCH;

    const char* Abase = Apk + (size_t)(m0 >> 7) * NCH * ATB;
    const char* Bbase = Bpk + (size_t)(n0 >> 6) * NCH * BTB;

    if (tid == 0) {
#pragma unroll
        for (int i = 0; i < 2; i++) {
            MBAR_INIT(smem_u32(&mbars[i]), 1);       // full: 1 tx-completion
            MBAR_INIT(smem_u32(&mbars[2 + i]), 4);   // empty: 4 warp arrivals
        }
    }
    __syncthreads();

    if (wid == 4) {
        // ---- producer warp ----
        if (lane == 0) {
            for (int c = 0; c < NC; c++) {
                int i = c & 1;
                if (c >= 2) MBAR_WAIT(smem_u32(&mbars[2 + i]), ((c >> 1) - 1) & 1);
                uint32_t mb = smem_u32(&mbars[i]);
                MBAR_EXPECT(mb, STAGEB);
                uint32_t dst = sb + (uint32_t)i * STAGEB;
                BULK_CP(dst,          Abase + (size_t)c * ATB, ATB, mb);
                BULK_CP(dst + 32768u, Bbase + (size_t)c * BTB, BTB, mb);
            }
        }
        return;
    }

    // ---- compute warps ----
    const int wm = wid >> 1;            // 0..1
    const int wn = wid & 1;             // 0..1
    const int a_r  = (lane & 7) + ((lane >> 3) & 1) * 8;
    const int a_cb = ((lane >> 4) & 1) * 16;
    const int b_r  = (lane & 7) + ((lane >> 4) & 1) * 8;
    const int b_cb = ((lane >> 3) & 1) * 16;

    float acc[4][4][4];
#pragma unroll
    for (int i = 0; i < 4; i++)
#pragma unroll
        for (int j = 0; j < 4; j++)
#pragma unroll
            for (int r = 0; r < 4; r++) acc[i][j][r] = 0.f;

    int buf = 0;
    for (int it = 0; it < NC; it++) {
        MBAR_WAIT(smem_u32(&mbars[buf]), (it >> 1) & 1);
        uint32_t stg = sb + (uint32_t)buf * STAGEB;

        uint32_t ah[2][4][4], al[2][4][4], bf[2][2][4];
        LOAD_FRAGS(0, 0);
        LOAD_FRAGS(1, 1); MMA_ALL(0);
        LOAD_FRAGS(0, 2); MMA_ALL(1);
        LOAD_FRAGS(1, 3); MMA_ALL(0);
        MMA_ALL(1);

        __syncwarp();
        if (lane == 0) MBAR_ARRIVE(smem_u32(&mbars[2 + buf]));
        buf ^= 1;
    }

    // ---- Epilogue ----
    const int gi = lane >> 2;
    const int ci = lane & 3;

    if (MODE == 2) {
        const bool isIF = (lane & 1) == 0;
        int rowm[4];
        float vv0[4], vv1[4];
#pragma unroll
        for (int mi = 0; mi < 4; mi++) {
            rowm[mi] = m0 + wm * 64 + mi * 16 + gi + (isIF ? 0 : 8);
            size_t vr = ((size_t)rowm[mi] * TT + t) * 2;
            vv0[mi] = v[vr];
            vv1[mi] = v[vr + 1];
        }
#pragma unroll
        for (int mi = 0; mi < 4; mi++)
#pragma unroll
            for (int ni = 0; ni < 4; ni++) {
                float c0 = acc[mi][ni][0], c1 = acc[mi][ni][1];
                float c2 = acc[mi][ni][2], c3 = acc[mi][ni][3];
                float o0 = __shfl_xor_sync(0xFFFFFFFFu, c0, 1);
                float o1 = __shfl_xor_sync(0xFFFFFFFFu, c1, 1);
                float o2 = __shfl_xor_sync(0xFFFFFFFFu, c2, 1);
                float o3 = __shfl_xor_sync(0xFFFFFFFFu, c3, 1);
                float zi = isIF ? c0 : o2;
                float zf = isIF ? c1 : o3;
                float zg = isIF ? o0 : c2;
                float zo = isIF ? o1 : c3;
                int row  = rowm[mi];
                int qcol = n0 + wn * 32 + ni * 8 + (ci >> 1) * 4;
                float4 q0 = *(const float4*)&d_W2pk[qcol];
                float4 q1 = *(const float4*)&d_W2pk[G4 + qcol];
                float4 qb = *(const float4*)&d_b2pk[qcol];
                zi += fmaf(vv0[mi], q0.x, fmaf(vv1[mi], q1.x, qb.x));
                zf += fmaf(vv0[mi], q0.y, fmaf(vv1[mi], q1.y, qb.y));
                zg += fmaf(vv0[mi], q0.z, fmaf(vv1[mi], q1.z, qb.z));
                zo += fmaf(vv0[mi], q0.w, fmaf(vv1[mi], q1.w, qb.w));
                float ig = sigmoidf_(zi);
                float fg = sigmoidf_(zf);
                float gg = fmaxf(zg, 0.f);
                float og = sigmoidf_(zo);
                int gcol = qcol >> 2;
                size_t cidx = (size_t)row * NG + gcol;
                float cn = fmaf(fg, c_state[cidx], ig * gg);
                c_state[cidx] = cn;
                float h = og * fmaxf(cn, 0.f);
                __half hh = __float2half(h);
                __half hl = __float2half(h - __half2float(hh));
                size_t ho = pk_off(row, gcol);
                *(__half*)(hpk_out + ho)         = hh;
                *(__half*)(hpk_out + ho + 16384) = hl;
                int hsrow = row * TT + t;
                size_t so = pk_off(hsrow, gcol);
                *(__half*)(hspk_out + so)         = hh;
                *(__half*)(hspk_out + so + 16384) = hl;
            }
    } else {
#pragma unroll
        for (int mi = 0; mi < 4; mi++)
#pragma unroll
            for (int ni = 0; ni < 4; ni++) {
                int row0 = m0 + wm * 64 + mi * 16 + gi;
                int col  = n0 + wn * 32 + ni * 8 + ci * 2;
                float bx = bias[col], by = bias[col + 1];
                float r0 = acc[mi][ni][0] + bx, r1 = acc[mi][ni][1] + by;
                float r2 = acc[mi][ni][2] + bx, r3 = acc[mi][ni][3] + by;
                if (MODE == 0) {
                    *(float2*)(Cout + (size_t)row0 * Nout + col)       = make_float2(r0, r1);
                    *(float2*)(Cout + (size_t)(row0 + 8) * Nout + col) = make_float2(r2, r3);
                } else {
                    r0 = fmaxf(r0, 0.f); r1 = fmaxf(r1, 0.f);
                    r2 = fmaxf(r2, 0.f); r3 = fmaxf(r3, 0.f);
                    __half h0 = __float2half(r0), h1 = __float2half(r1);
                    __half h2 = __float2half(r2), h3 = __float2half(r3);
                    size_t o0 = pk_off(row0, col);
                    size_t o1 = pk_off(row0 + 8, col);
                    *(__half2*)(gpk_out + o0) = __halves2half2(h0, h1);
                    *(__half2*)(gpk_out + o1) = __halves2half2(h2, h3);
                    *(__half2*)(gpk_out + o0 + 16384) = __halves2half2(
                        __float2half(r0 - __half2float(h0)),
                        __float2half(r1 - __half2float(h1)));
                    *(__half2*)(gpk_out + o1 + 16384) = __halves2half2(
                        __float2half(r2 - __half2float(h2)),
                        __float2half(r3 - __half2float(h3)));
                }
            }
    }
}

// ---------------------------------------------------------------------------
extern "C" void kernel_launch(void* const* d_in, const int* in_sizes, int n_in,
                              void* d_out, int out_size) {
    const float* v       = (const float*)d_in[0];
    const float* p0      = (const float*)d_in[1];
    const float* enc1_W  = (const float*)d_in[2];
    const float* enc1_b  = (const float*)d_in[3];
    const float* enc2_W  = (const float*)d_in[4];
    const float* enc2_b  = (const float*)d_in[5];
    const float* M_W     = (const float*)d_in[6];
    const float* M_b     = (const float*)d_in[7];
    const float* lstm_W  = (const float*)d_in[8];
    const float* lstm_U  = (const float*)d_in[9];
    const float* lstm_b  = (const float*)d_in[10];
    const float* dense_W = (const float*)d_in[11];
    const float* dense_b = (const float*)d_in[12];
    const float* dec_W   = (const float*)d_in[13];
    const float* dec_b   = (const float*)d_in[14];
    float* out = (float*)d_out;

    char *Upk, *DWpk, *DCpk, *hpk, *hspk, *gpk;
    float *cp;
    cudaGetSymbolAddress((void**)&Upk,  d_Upk);
    cudaGetSymbolAddress((void**)&DWpk, d_DWpk);
    cudaGetSymbolAddress((void**)&DCpk, d_DCpk);
    cudaGetSymbolAddress((void**)&hpk,  d_hpk);
    cudaGetSymbolAddress((void**)&hspk, d_hspk);
    cudaGetSymbolAddress((void**)&gpk,  d_gpk);
    cudaGetSymbolAddress((void**)&cp,   d_cbuf);

    const int SMEMSZ = 2 * STAGEB;  // 80 KB -> 2 CTAs/SM
    cudaFuncSetAttribute(hmma_gemm<0>, cudaFuncAttributeMaxDynamicSharedMemorySize, SMEMSZ);
    cudaFuncSetAttribute(hmma_gemm<1>, cudaFuncAttributeMaxDynamicSharedMemorySize, SMEMSZ);
    cudaFuncSetAttribute(hmma_gemm<2>, cudaFuncAttributeMaxDynamicSharedMemorySize, SMEMSZ);

    // 1) Weight prep
    prep_w2_k<<<G4 / 256, 256>>>(lstm_W, lstm_b, M_W, M_b);
    transp_split_all<<<21504, dim3(32, 8)>>>(lstm_U, dense_W, dec_W);

    // 2) Initial state: h0 packed split fp16 + c0 fp32
    enc_k<<<dim3(NG / 64, BB / 128, 2), 256>>>(p0, enc1_W, enc1_b, enc2_W, enc2_b,
                                               hpk, cp);

    // 3) Recurrence: 100 HMMA steps, 2 CTAs/SM, warp-specialized, 2-product fp16
    const size_t HP = (size_t)(BB / 128) * NCH * ATB;
    for (int tstep = 0; tstep < TT; tstep++) {
        int pi = tstep & 1, po = (tstep + 1) & 1;
        hmma_gemm<2><<<dim3(G4 / 64, BB / 128), 160, SMEMSZ>>>(
            hpk + pi * HP, Upk, nullptr, nullptr, 0,
            v, cp, hpk + po * HP, hspk, nullptr, tstep);
    }

    // 4) dense: g = relu(hs @ dense_W + b) -> packed split fp16
    hmma_gemm<1><<<dim3(NG / 64, MTR / 128), 160, SMEMSZ>>>(
        hspk, DWpk, dense_b, nullptr, 0,
        nullptr, nullptr, nullptr, nullptr, gpk, 0);

    // 5) dec: out = g @ dec_W + b -> fp32
    hmma_gemm<0><<<dim3(NP / 64, MTR / 128), 160, SMEMSZ>>>(
        gpk, DCpk, dec_b, out, NP,
        nullptr, nullptr, nullptr, nullptr, nullptr, 0);
}